// round 12
// baseline (speedup 1.0000x reference)
#include <cuda_runtime.h>
#include <cstdint>
#include <cstddef>
#include <math.h>

#define B_   8
#define NQ_  1024
#define NKV_ 1024
#define DQ_  512
#define H_   8
#define DH_  64
#define BH_  64

// Prepacked bf16 hi/lo operand arrays: [bh][n][32] u32 words
__device__ uint32_t g_Qh[BH_ * NQ_ * 32];
__device__ uint32_t g_Ql[BH_ * NQ_ * 32];
__device__ uint32_t g_Kh[BH_ * NKV_ * 32];
__device__ uint32_t g_Kl[BH_ * NKV_ * 32];
__device__ float    g_Vp[BH_ * NKV_ * DH_];
__device__ float    g_Obuf[B_ * NQ_ * H_ * DH_];
__device__ float    g_attn_scratch[(size_t)BH_ * NQ_ * NKV_];

__device__ __forceinline__ uint32_t packbf(float x0, float x1) {
    uint32_t r;
    asm("cvt.rn.bf16x2.f32 %0, %1, %2;" : "=r"(r) : "f"(x1), "f"(x0));
    return r;
}
__device__ __forceinline__ float bf_lo(uint32_t r) { return __uint_as_float(r << 16); }
__device__ __forceinline__ float bf_hi(uint32_t r) { return __uint_as_float(r & 0xffff0000u); }

__device__ __forceinline__ void mma16(float* c, const uint32_t* a, const uint32_t* b) {
    asm volatile(
        "mma.sync.aligned.m16n8k16.row.col.f32.bf16.bf16.f32 "
        "{%0,%1,%2,%3},{%4,%5,%6,%7},{%8,%9},{%0,%1,%2,%3};"
        : "+f"(c[0]), "+f"(c[1]), "+f"(c[2]), "+f"(c[3])
        : "r"(a[0]), "r"(a[1]), "r"(a[2]), "r"(a[3]), "r"(b[0]), "r"(b[1]));
}

__device__ __forceinline__ void cp16(uint32_t dst, const void* src) {
    asm volatile("cp.async.ca.shared.global [%0], [%1], 16;" :: "r"(dst), "l"(src));
}
#define CP_COMMIT() asm volatile("cp.async.commit_group;")
#define CP_WAIT0()  asm volatile("cp.async.wait_group 0;")

// ---------------------------------------------------------------------------
// Generic GEMM on bf16 tensor cores with split-bf16 accuracy.
// EPI: 0 store(+bias), 1 QKV fp32 scatter(+bias), 4 bf16x2 bias store,
//      5 QKV packed hi/lo scatter(+bias), 6 = EPI4 + mask folded (-inf bf16).
// ---------------------------------------------------------------------------
template <int BM, int BN, int BK, int WM, int WN, bool BCOL, int EPI, int NSPLIT,
          int MINBLK = 1, bool APACK = false>
__global__ __launch_bounds__(256, MINBLK) void mma_gemm(
    const float* __restrict__ A, const float* __restrict__ Bg,
    const float* __restrict__ bias, float* __restrict__ C,
    float* __restrict__ C2, const int* __restrict__ maskp,
    int K, long lda, long ldb, long ldc, long sA, long sB, long sC)
{
    constexpr int MT = WM / 16, NT = WN / 8;
    constexpr int WX = BN / WN;
    constexpr int KW = BK / 2;
    constexpr bool SPL = (NSPLIT == 3);
    constexpr int BR  = BCOL ? BN : KW;
    constexpr int BCW = BCOL ? (KW + 4) : (BN + 8);

    __shared__ uint32_t sAh[BM][KW + 4];
    __shared__ uint32_t sAl[SPL ? BM : 1][SPL ? KW + 4 : 1];
    __shared__ uint32_t sBh[BR][BCW];
    __shared__ uint32_t sBl[SPL ? BR : 1][SPL ? BCW : 1];

    const int tid = threadIdx.x;
    const int warp = tid >> 5, lane = tid & 31;
    const int wx = warp % WX, wy = warp / WX;
    const long z = blockIdx.z;

    const float* Ab = APACK ? nullptr : (A + z * sA + (long)blockIdx.y * BM * lda);
    const uint32_t* Abw = APACK ? ((const uint32_t*)A + z * sA + (long)blockIdx.y * BM * lda)
                                : nullptr;
    const float* Bb = BCOL ? (Bg + z * sB + (long)blockIdx.x * BN * ldb)
                           : (Bg + z * sB + (long)blockIdx.x * BN);

    float acc[MT * NT][4];
#pragma unroll
    for (int i = 0; i < MT * NT; i++)
#pragma unroll
        for (int r = 0; r < 4; r++) acc[i][r] = 0.0f;

    for (int k0 = 0; k0 < K; k0 += BK) {
        if (APACK) {
            constexpr int TOT = BM * (KW / 4);
#pragma unroll
            for (int it = 0; it < (TOT + 255) / 256; it++) {
                int idx = tid + it * 256;
                if (TOT % 256 != 0 && idx >= TOT) break;
                int m = idx / (KW / 4), w4 = (idx % (KW / 4)) * 4;
                uint4 v = *(const uint4*)(Abw + (long)m * lda + (k0 >> 1) + w4);
                *(uint4*)&sAh[m][w4] = v;
            }
        } else {
            constexpr int AIT = (BM * BK / 4) / 256;
#pragma unroll
            for (int it = 0; it < AIT; it++) {
                int idx = tid + it * 256;
                int m = idx / (BK / 4), kq = idx % (BK / 4);
                float4 v = *(const float4*)(Ab + (long)m * lda + k0 + kq * 4);
                uint32_t h0 = packbf(v.x, v.y), h1 = packbf(v.z, v.w);
                sAh[m][kq * 2] = h0; sAh[m][kq * 2 + 1] = h1;
                if (SPL) {
                    sAl[m][kq * 2]     = packbf(v.x - bf_lo(h0), v.y - bf_hi(h0));
                    sAl[m][kq * 2 + 1] = packbf(v.z - bf_lo(h1), v.w - bf_hi(h1));
                }
            }
        }
        if (BCOL) {
            constexpr int BIT = (BN * BK / 4) / 256;
#pragma unroll
            for (int it = 0; it < BIT; it++) {
                int idx = tid + it * 256;
                int n = idx / (BK / 4), kq = idx % (BK / 4);
                float4 v = *(const float4*)(Bb + (long)n * ldb + k0 + kq * 4);
                uint32_t h0 = packbf(v.x, v.y), h1 = packbf(v.z, v.w);
                sBh[n][kq * 2] = h0; sBh[n][kq * 2 + 1] = h1;
                if (SPL) {
                    sBl[n][kq * 2]     = packbf(v.x - bf_lo(h0), v.y - bf_hi(h0));
                    sBl[n][kq * 2 + 1] = packbf(v.z - bf_lo(h1), v.w - bf_hi(h1));
                }
            }
        } else {
            constexpr int BIT = (KW * (BN / 4) + 255) / 256;
#pragma unroll
            for (int it = 0; it < BIT; it++) {
                int idx = tid + it * 256;
                if (KW * (BN / 4) % 256 != 0 && idx >= KW * (BN / 4)) break;
                int kp = idx / (BN / 4), n4 = (idx % (BN / 4)) * 4;
                float4 v0 = *(const float4*)(Bb + (long)(k0 + kp * 2) * ldb + n4);
                float4 v1 = *(const float4*)(Bb + (long)(k0 + kp * 2 + 1) * ldb + n4);
                uint32_t h0 = packbf(v0.x, v1.x), h1 = packbf(v0.y, v1.y);
                uint32_t h2 = packbf(v0.z, v1.z), h3 = packbf(v0.w, v1.w);
                sBh[kp][n4 + 0] = h0; sBh[kp][n4 + 1] = h1;
                sBh[kp][n4 + 2] = h2; sBh[kp][n4 + 3] = h3;
                if (SPL) {
                    sBl[kp][n4 + 0] = packbf(v0.x - bf_lo(h0), v1.x - bf_hi(h0));
                    sBl[kp][n4 + 1] = packbf(v0.y - bf_lo(h1), v1.y - bf_hi(h1));
                    sBl[kp][n4 + 2] = packbf(v0.z - bf_lo(h2), v1.z - bf_hi(h2));
                    sBl[kp][n4 + 3] = packbf(v0.w - bf_lo(h3), v1.w - bf_hi(h3));
                }
            }
        }
        __syncthreads();

#pragma unroll
        for (int kc = 0; kc < KW; kc += 8) {
            const int kb = kc + (lane & 3);
            const int mrow = wy * WM + (lane >> 2);
            uint32_t afh[MT][4], afl[MT][4];
#pragma unroll
            for (int i = 0; i < MT; i++) {
                int m = mrow + i * 16;
                afh[i][0] = sAh[m][kb];     afh[i][1] = sAh[m + 8][kb];
                afh[i][2] = sAh[m][kb + 4]; afh[i][3] = sAh[m + 8][kb + 4];
                if (SPL) {
                    afl[i][0] = sAl[m][kb];     afl[i][1] = sAl[m + 8][kb];
                    afl[i][2] = sAl[m][kb + 4]; afl[i][3] = sAl[m + 8][kb + 4];
                }
            }
#pragma unroll
            for (int j = 0; j < NT; j++) {
                uint32_t bfh[2], bfl[2];
                int n = wx * WN + j * 8 + (lane >> 2);
                if (BCOL) {
                    bfh[0] = sBh[n][kb]; bfh[1] = sBh[n][kb + 4];
                    if (SPL) { bfl[0] = sBl[n][kb]; bfl[1] = sBl[n][kb + 4]; }
                } else {
                    bfh[0] = sBh[kb][n]; bfh[1] = sBh[kb + 4][n];
                    if (SPL) { bfl[0] = sBl[kb][n]; bfl[1] = sBl[kb + 4][n]; }
                }
#pragma unroll
                for (int i = 0; i < MT; i++) {
                    mma16(acc[i * NT + j], afh[i], bfh);
                    if (SPL) {
                        mma16(acc[i * NT + j], afh[i], bfl);
                        mma16(acc[i * NT + j], afl[i], bfh);
                    }
                }
            }
        }
        __syncthreads();
    }

    const long m0 = (long)blockIdx.y * BM + wy * WM;
    const long n0 = (long)blockIdx.x * BN + wx * WN;
    float* Cb = C + z * sC;
    long ldcc = ldc;

#pragma unroll
    for (int i = 0; i < MT; i++) {
#pragma unroll
        for (int j = 0; j < NT; j++) {
#pragma unroll
            for (int r2 = 0; r2 < 2; r2++) {
                long row = m0 + i * 16 + r2 * 8 + (lane >> 2);
                long col = n0 + j * 8 + (lane & 3) * 2;
                float v0 = acc[i * NT + j][r2 * 2 + 0];
                float v1 = acc[i * NT + j][r2 * 2 + 1];
                if ((EPI == 0 || EPI == 1) && bias) { v0 += bias[col]; v1 += bias[col + 1]; }
                if (EPI == 1) {
                    long bb = row >> 10, ns = row & 1023;
                    long h = col >> 6, d = col & 63;
                    float* p = C + (((bb * 8 + h) * 1024 + ns) * 64 + d);
                    *(float2*)p = make_float2(v0, v1);
                } else if (EPI == 4 || EPI == 6) {
                    uint32_t hw = packbf(v0, v1);
                    if (EPI == 6) {
                        const int* mp = maskp + (row >> 3) * 1024 + col;
                        int mm0 = __ldg(mp), mm1 = __ldg(mp + 1);
                        if (!mm0) hw = (hw & 0xFFFF0000u) | 0x0000FF80u;  // bf16 -inf
                        if (!mm1) hw = (hw & 0x0000FFFFu) | 0xFF800000u;
                    }
                    uint32_t* P = (uint32_t*)C;
                    __stcs(P + row * ldcc + z * sC + (col >> 1), hw);
                } else if (EPI == 5) {
                    float w0 = v0 + (bias ? bias[col] : 0.0f);
                    float w1 = v1 + (bias ? bias[col + 1] : 0.0f);
                    uint32_t hw = packbf(w0, w1);
                    uint32_t lw = packbf(w0 - bf_lo(hw), w1 - bf_hi(hw));
                    long bb = row >> 10, ns = row & 1023;
                    long hh = col >> 6, d = col & 63;
                    long widx = ((bb * 8 + hh) * 1024 + ns) * 32 + (d >> 1);
                    ((uint32_t*)C)[widx]  = hw;
                    ((uint32_t*)C2)[widx] = lw;
                } else {
                    *(float2*)(Cb + row * ldcc + col) = make_float2(v0, v1);
                }
            }
        }
    }
}

// ---------------------------------------------------------------------------
// Flash-style fused attention, coalesced gmem: bias staged via cp.async into
// smem; attn written via smem bounce with lane-contiguous float4 stcs.
// 256 threads, 2 blocks/SM.  Grid (NQ/32, BH).
// ---------------------------------------------------------------------------
#define OQH   0
#define OQL   (32*36)
#define OKH   (2*32*36)
#define OKL   (OKH + 128*36)
#define OVH   (OKL + 128*36)
#define OVL   (OVH + 64*68)
#define OBIAS (OVL + 64*68)          // u32 [32][68] bias tile
#define OPST  (OBIAS + 32*68)        // f32 [32][132] P stage
#define ORED  (OPST + 32*132)        // float2[32][8]
#define OFIN  (ORED + 512)           // float2[32]
#define FLASH_WORDS (OFIN + 64)      // 27200 words = 108800 B

__global__ __launch_bounds__(256, 2) void fused_flash(
    const uint32_t* __restrict__ Qhw, const uint32_t* __restrict__ Qlw,
    const uint32_t* __restrict__ Khw, const uint32_t* __restrict__ Klw,
    const float* __restrict__ Vp, const uint32_t* __restrict__ biasw,
    float* __restrict__ attn, float* __restrict__ Obuf)
{
    extern __shared__ uint32_t sm[];
    uint32_t* sQh = sm + OQH;
    uint32_t* sQl = sm + OQL;
    uint32_t* sKh = sm + OKH;
    uint32_t* sKl = sm + OKL;
    uint32_t* sVh = sm + OVH;
    uint32_t* sVl = sm + OVL;
    uint32_t* sBi = sm + OBIAS;
    float*    sPst = (float*)(sm + OPST);
    float2*   red = (float2*)(sm + ORED);
    float2*   fin = (float2*)(sm + OFIN);
    const uint32_t smb = (uint32_t)__cvta_generic_to_shared(sm);

    const int tid = threadIdx.x, warp = tid >> 5, lane = tid & 31;
    const int q0 = blockIdx.x * 32, bh = blockIdx.y;
    const int b = bh >> 3, h = bh & 7;

    const uint32_t* QhB = Qhw + (size_t)bh * 32768 + q0 * 32;
    const uint32_t* QlB = Qlw + (size_t)bh * 32768 + q0 * 32;
    const uint32_t* KhB = Khw + (size_t)bh * 32768;
    const uint32_t* KlB = Klw + (size_t)bh * 32768;
    const float* Vb = Vp + (size_t)bh * 65536;
    float* attnb = attn + (size_t)bh * 1048576 + (size_t)q0 * 1024;
    const uint32_t* biasb = biasw + (size_t)bh * 524288 + (size_t)q0 * 512;

    // stage Q once
    {
        int m = tid >> 3, w = (tid & 7) * 4;
        *(uint4*)&sQh[m * 36 + w] = *(const uint4*)(QhB + m * 32 + w);
        *(uint4*)&sQl[m * 36 + w] = *(const uint4*)(QlB + m * 32 + w);
    }

    const int r4 = lane >> 2;
    const int lc = lane & 3;
    const int wb = warp * 8;

    // ======================= PASS A: row max & sum =======================
    float mA[4] = {-1e30f, -1e30f, -1e30f, -1e30f};
    float sA[4] = {0.f, 0.f, 0.f, 0.f};

    for (int kt = 0; kt < 8; kt++) {
#pragma unroll
        for (int c = 0; c < 4; c++) {
            int f = tid + c * 256;
            int r = f >> 3, ch = (f & 7) * 4;
            cp16(smb + (OKH + r * 36 + ch) * 4, KhB + kt * 4096 + r * 32 + ch);
            cp16(smb + (OKL + r * 36 + ch) * 4, KlB + kt * 4096 + r * 32 + ch);
        }
#pragma unroll
        for (int i = 0; i < 2; i++) {   // bias tile, coalesced
            int f = tid + i * 256;
            int row = f >> 4, w4 = (f & 15) * 4;
            cp16(smb + (OBIAS + row * 68 + w4) * 4, biasb + row * 512 + kt * 64 + w4);
        }
        CP_COMMIT();
        CP_WAIT0();
        __syncthreads();

        float acc[2][2][4] = {};
#pragma unroll
        for (int c = 0; c < 4; c++) {
            int kb = c * 8 + lc;
            uint32_t ah[2][4], al[2][4];
#pragma unroll
            for (int mi = 0; mi < 2; mi++) {
                int m = mi * 16 + r4;
                ah[mi][0] = sQh[m * 36 + kb];     ah[mi][1] = sQh[(m + 8) * 36 + kb];
                ah[mi][2] = sQh[m * 36 + kb + 4]; ah[mi][3] = sQh[(m + 8) * 36 + kb + 4];
                al[mi][0] = sQl[m * 36 + kb];     al[mi][1] = sQl[(m + 8) * 36 + kb];
                al[mi][2] = sQl[m * 36 + kb + 4]; al[mi][3] = sQl[(m + 8) * 36 + kb + 4];
            }
#pragma unroll
            for (int nt = 0; nt < 2; nt++) {
                int n = warp * 16 + nt * 8 + r4;
                uint32_t bfh[2] = { sKh[n * 36 + kb], sKh[n * 36 + kb + 4] };
                uint32_t bfl[2] = { sKl[n * 36 + kb], sKl[n * 36 + kb + 4] };
#pragma unroll
                for (int mi = 0; mi < 2; mi++) {
                    mma16(acc[mi][nt], ah[mi], bfh);
                    mma16(acc[mi][nt], ah[mi], bfl);
                    mma16(acc[mi][nt], al[mi], bfh);
                }
            }
        }
#pragma unroll
        for (int mi = 0; mi < 2; mi++)
#pragma unroll
            for (int rh = 0; rh < 2; rh++) {
                int row = mi * 16 + rh * 8 + r4;
                int s = mi * 2 + rh;
                uint32_t bw0 = sBi[row * 68 + wb + lc];
                uint32_t bw1 = sBi[row * 68 + wb + 4 + lc];
                float x0 = (acc[mi][0][rh * 2 + 0] + bf_lo(bw0)) * 0.125f;
                float x1 = (acc[mi][0][rh * 2 + 1] + bf_hi(bw0)) * 0.125f;
                float x2 = (acc[mi][1][rh * 2 + 0] + bf_lo(bw1)) * 0.125f;
                float x3 = (acc[mi][1][rh * 2 + 1] + bf_hi(bw1)) * 0.125f;
                float vm = fmaxf(fmaxf(x0, x1), fmaxf(x2, x3));
                float nm = fmaxf(mA[s], vm);
                sA[s] = sA[s] * __expf(mA[s] - nm)
                      + __expf(x0 - nm) + __expf(x1 - nm)
                      + __expf(x2 - nm) + __expf(x3 - nm);
                mA[s] = nm;
            }
        __syncthreads();
    }

#pragma unroll
    for (int s = 0; s < 4; s++) {
#pragma unroll
        for (int off = 1; off <= 2; off <<= 1) {
            float mo = __shfl_xor_sync(0xffffffffu, mA[s], off);
            float so = __shfl_xor_sync(0xffffffffu, sA[s], off);
            float nm = fmaxf(mA[s], mo);
            sA[s] = sA[s] * __expf(mA[s] - nm) + so * __expf(mo - nm);
            mA[s] = nm;
        }
    }
    if (lc == 0) {
#pragma unroll
        for (int s = 0; s < 4; s++) {
            int row = (s >> 1) * 16 + (s & 1) * 8 + r4;
            red[row * 8 + warp] = make_float2(mA[s], sA[s]);
        }
    }
    __syncthreads();
    if (tid < 32) {
        float m = -1e30f, s = 0.f;
#pragma unroll
        for (int w = 0; w < 8; w++) {
            float2 e = red[tid * 8 + w];
            float nm = fmaxf(m, e.x);
            s = s * __expf(m - nm) + e.y * __expf(e.x - nm);
            m = nm;
        }
        fin[tid] = make_float2(m, 1.0f / s);
    }
    __syncthreads();

    float fm[4], fi[4];
#pragma unroll
    for (int s = 0; s < 4; s++) {
        float2 e = fin[(s >> 1) * 16 + (s & 1) * 8 + r4];
        fm[s] = e.x; fi[s] = e.y;
    }

    // ======================= PASS B: attn out + O = P V ==================
    float accO[2][8][4] = {};
    for (int kt = 0; kt < 8; kt++) {
#pragma unroll
        for (int c = 0; c < 4; c++) {
            int f = tid + c * 256;
            int r = f >> 3, ch = (f & 7) * 4;
            cp16(smb + (OKH + r * 36 + ch) * 4, KhB + kt * 4096 + r * 32 + ch);
            cp16(smb + (OKL + r * 36 + ch) * 4, KlB + kt * 4096 + r * 32 + ch);
        }
#pragma unroll
        for (int i = 0; i < 2; i++) {   // bias tile, coalesced
            int f = tid + i * 256;
            int row = f >> 4, w4 = (f & 15) * 4;
            cp16(smb + (OBIAS + row * 68 + w4) * 4, biasb + row * 512 + kt * 64 + w4);
        }
        CP_COMMIT();
#pragma unroll
        for (int t = 0; t < 4; t++) {
            int f = tid + t * 256;
            int p = f >> 4, d4 = (f & 15) * 4;
            const float* vp0 = Vb + (kt * 128 + 2 * p) * 64 + d4;
            float4 v0 = *(const float4*)vp0;
            float4 v1 = *(const float4*)(vp0 + 64);
            uint32_t w0 = packbf(v0.x, v1.x), w1 = packbf(v0.y, v1.y);
            uint32_t w2 = packbf(v0.z, v1.z), w3 = packbf(v0.w, v1.w);
            sVh[(d4 + 0) * 68 + p] = w0; sVh[(d4 + 1) * 68 + p] = w1;
            sVh[(d4 + 2) * 68 + p] = w2; sVh[(d4 + 3) * 68 + p] = w3;
            sVl[(d4 + 0) * 68 + p] = packbf(v0.x - bf_lo(w0), v1.x - bf_hi(w0));
            sVl[(d4 + 1) * 68 + p] = packbf(v0.y - bf_lo(w1), v1.y - bf_hi(w1));
            sVl[(d4 + 2) * 68 + p] = packbf(v0.z - bf_lo(w2), v1.z - bf_hi(w2));
            sVl[(d4 + 3) * 68 + p] = packbf(v0.w - bf_lo(w3), v1.w - bf_hi(w3));
        }
        CP_WAIT0();
        __syncthreads();

        // QK recompute
        float acc[2][2][4] = {};
#pragma unroll
        for (int c = 0; c < 4; c++) {
            int kb = c * 8 + lc;
            uint32_t ah[2][4], al[2][4];
#pragma unroll
            for (int mi = 0; mi < 2; mi++) {
                int m = mi * 16 + r4;
                ah[mi][0] = sQh[m * 36 + kb];     ah[mi][1] = sQh[(m + 8) * 36 + kb];
                ah[mi][2] = sQh[m * 36 + kb + 4]; ah[mi][3] = sQh[(m + 8) * 36 + kb + 4];
                al[mi][0] = sQl[m * 36 + kb];     al[mi][1] = sQl[(m + 8) * 36 + kb];
                al[mi][2] = sQl[m * 36 + kb + 4]; al[mi][3] = sQl[(m + 8) * 36 + kb + 4];
            }
#pragma unroll
            for (int nt = 0; nt < 2; nt++) {
                int n = warp * 16 + nt * 8 + r4;
                uint32_t bfh[2] = { sKh[n * 36 + kb], sKh[n * 36 + kb + 4] };
                uint32_t bfl[2] = { sKl[n * 36 + kb], sKl[n * 36 + kb + 4] };
#pragma unroll
                for (int mi = 0; mi < 2; mi++) {
                    mma16(acc[mi][nt], ah[mi], bfh);
                    mma16(acc[mi][nt], ah[mi], bfl);
                    mma16(acc[mi][nt], al[mi], bfh);
                }
            }
        }

        // normalize, stage P into smem (fp32) + pack P regs, AV accumulate
        uint32_t pfh[2][4], pfl[2][4];
#pragma unroll
        for (int mi = 0; mi < 2; mi++) {
            float p[2][4];
#pragma unroll
            for (int rh = 0; rh < 2; rh++) {
                int row = mi * 16 + rh * 8 + r4;
                int s = mi * 2 + rh;
                uint32_t bw0 = sBi[row * 68 + wb + lc];
                uint32_t bw1 = sBi[row * 68 + wb + 4 + lc];
                float x0 = (acc[mi][0][rh * 2 + 0] + bf_lo(bw0)) * 0.125f;
                float x1 = (acc[mi][0][rh * 2 + 1] + bf_hi(bw0)) * 0.125f;
                float x2 = (acc[mi][1][rh * 2 + 0] + bf_lo(bw1)) * 0.125f;
                float x3 = (acc[mi][1][rh * 2 + 1] + bf_hi(bw1)) * 0.125f;
                float p0 = __expf(x0 - fm[s]) * fi[s];
                float p1 = __expf(x1 - fm[s]) * fi[s];
                float p2 = __expf(x2 - fm[s]) * fi[s];
                float p3 = __expf(x3 - fm[s]) * fi[s];
                int colL = warp * 16 + 2 * lc;
                *(float2*)&sPst[row * 132 + colL]     = make_float2(p0, p1);
                *(float2*)&sPst[row * 132 + colL + 8] = make_float2(p2, p3);
                p[0][rh * 2] = p0; p[0][rh * 2 + 1] = p1;
                p[1][rh * 2] = p2; p[1][rh * 2 + 1] = p3;
            }
            pfh[mi][0] = packbf(p[0][0], p[0][1]); pfh[mi][1] = packbf(p[0][2], p[0][3]);
            pfh[mi][2] = packbf(p[1][0], p[1][1]); pfh[mi][3] = packbf(p[1][2], p[1][3]);
            pfl[mi][0] = packbf(p[0][0] - bf_lo(pfh[mi][0]), p[0][1] - bf_hi(pfh[mi][0]));
            pfl[mi][1] = packbf(p[0][2] - bf_lo(pfh[mi][1]), p[0][3] - bf_hi(pfh[mi][1]));
            pfl[mi][2] = packbf(p[1][0] - bf_lo(pfh[mi][2]), p[1][1] - bf_hi(pfh[mi][2]));
            pfl[mi][3] = packbf(p[1][2] - bf_lo(pfh[mi][3]), p[1][3] - bf_hi(pfh[mi][3]));
        }
#pragma unroll
        for (int dt = 0; dt < 8; dt++) {
            int n = dt * 8 + r4;
            uint32_t bvh[2] = { sVh[n * 68 + wb + lc], sVh[n * 68 + wb + lc + 4] };
            uint32_t bvl[2] = { sVl[n * 68 + wb + lc], sVl[n * 68 + wb + lc + 4] };
#pragma unroll
            for (int mi = 0; mi < 2; mi++) {
                mma16(accO[mi][dt], pfh[mi], bvh);
                mma16(accO[mi][dt], pfh[mi], bvl);
                mma16(accO[mi][dt], pfl[mi], bvh);
            }
        }
        __syncthreads();   // P stage complete; K/V/bias consumed

        // coalesced attn store from sPst (lane-contiguous float4)
#pragma unroll
        for (int i = 0; i < 4; i++) {
            int f = tid + i * 256;
            int row = f >> 5, c4 = (f & 31) * 4;
            float4 v = *(float4*)&sPst[row * 132 + c4];
            __stcs((float4*)(attnb + (size_t)row * 1024 + kt * 128 + c4), v);
        }
    }

    // cross-warp O reduction (reuse smem)
    __syncthreads();
    float* Ored = (float*)sm;
#pragma unroll
    for (int mi = 0; mi < 2; mi++)
#pragma unroll
        for (int dt = 0; dt < 8; dt++) {
            int row = mi * 16 + r4;
            int col = dt * 8 + 2 * lc;
            *(float2*)&Ored[warp * 2048 + row * 64 + col] =
                make_float2(accO[mi][dt][0], accO[mi][dt][1]);
            *(float2*)&Ored[warp * 2048 + (row + 8) * 64 + col] =
                make_float2(accO[mi][dt][2], accO[mi][dt][3]);
        }
    __syncthreads();
#pragma unroll
    for (int j = 0; j < 2; j++) {
        int base = tid * 8 + j * 4;
        float4 s4 = make_float4(0.f, 0.f, 0.f, 0.f);
#pragma unroll
        for (int w = 0; w < 8; w++) {
            float4 v = *(float4*)&Ored[w * 2048 + base];
            s4.x += v.x; s4.y += v.y; s4.z += v.z; s4.w += v.w;
        }
        int row = base >> 6, d = base & 63;
        *(float4*)&Obuf[(size_t)(b * 1024 + q0 + row) * 512 + h * 64 + d] = s4;
    }
}

// ---------------------------------------------------------------------------
extern "C" void kernel_launch(void* const* d_in, const int* in_sizes, int n_in,
                              void* d_out, int out_size)
{
    const float* q    = (const float*)d_in[0];
    const float* kv   = (const float*)d_in[1];
    const int*   mask = (const int*)d_in[2];
    const float* Wq   = (const float*)d_in[3];
    const float* bq   = (const float*)d_in[4];
    const float* Wk   = (const float*)d_in[5];
    const float* bk   = (const float*)d_in[6];
    const float* Wv   = (const float*)d_in[7];
    const float* bv   = (const float*)d_in[8];
    const float* Wo   = (const float*)d_in[9];
    const float* bo   = (const float*)d_in[10];
    const float* R    = (const float*)d_in[11];

    float* out = (float*)d_out;
    const size_t OUT0_ELEMS = (size_t)B_ * NQ_ * DQ_;
    const size_t ATTN_ELEMS = (size_t)BH_ * NQ_ * NKV_;

    uint32_t *Qh, *Ql, *Kh, *Kl;
    float *Vp, *Ob, *scr;
    cudaGetSymbolAddress((void**)&Qh, g_Qh);
    cudaGetSymbolAddress((void**)&Ql, g_Ql);
    cudaGetSymbolAddress((void**)&Kh, g_Kh);
    cudaGetSymbolAddress((void**)&Kl, g_Kl);
    cudaGetSymbolAddress((void**)&Vp, g_Vp);
    cudaGetSymbolAddress((void**)&Ob, g_Obuf);
    cudaGetSymbolAddress((void**)&scr, g_attn_scratch);

    float* attn = ((size_t)out_size >= OUT0_ELEMS + ATTN_ELEMS) ? (out + OUT0_ELEMS)
                                                                : scr + ATTN_ELEMS / 2;
    uint32_t* biasw = (uint32_t*)scr;

    static cudaStream_t s1 = nullptr, s2 = nullptr;
    static cudaEvent_t eRoot, e1, e2;
    static int init_done = 0;
    if (!init_done) {
        cudaFuncSetAttribute(fused_flash, cudaFuncAttributeMaxDynamicSharedMemorySize,
                             FLASH_WORDS * 4);
        cudaStreamCreateWithFlags(&s1, cudaStreamNonBlocking);
        cudaStreamCreateWithFlags(&s2, cudaStreamNonBlocking);
        cudaEventCreateWithFlags(&eRoot, cudaEventDisableTiming);
        cudaEventCreateWithFlags(&e1, cudaEventDisableTiming);
        cudaEventCreateWithFlags(&e2, cudaEventDisableTiming);
        init_done = 1;
    }

    cudaEventRecord(eRoot, 0);
    cudaStreamWaitEvent(s1, eRoot, 0);
    cudaStreamWaitEvent(s2, eRoot, 0);

    // K projection -> packed hi/lo  (side stream)
    mma_gemm<128,128,32,64,32,false,5,3><<<dim3(4,64,1),256,0,s1>>>(
        kv, Wk, bk, (float*)Kh, (float*)Kl, nullptr, 512, 512, 512, 0, 0, 0, 0);
    // V projection -> fp32 scatter  (side stream)
    mma_gemm<128,128,32,64,32,false,1,3><<<dim3(4,64,1),256,0,s2>>>(
        kv, Wv, bv, Vp, nullptr, nullptr, 512, 512, 512, 0, 0, 0, 0);

    // Q projection -> packed hi/lo  (main stream)
    mma_gemm<128,128,32,64,32,false,5,3><<<dim3(4,64,1),256>>>(
        q, Wq, bq, (float*)Qh, (float*)Ql, nullptr, 512, 512, 512, 0, 0, 0, 0);

    // RPE bias + mask fold -> bf16x2 bias (APACK, NSPLIT=1, MINBLK=4)
    mma_gemm<64,128,32,32,32,true,6,1,4,true><<<dim3(8,1,1024),256>>>(
        (const float*)Qh, R, nullptr, (float*)biasw, nullptr, mask, 64,
        /*lda(words)=*/32768, /*ldb=*/64, /*ldc=*/524288,
        /*sA(words)=*/32, /*sB=*/65536, /*sC=*/512);

    cudaEventRecord(e1, s1);
    cudaEventRecord(e2, s2);
    cudaStreamWaitEvent(0, e1, 0);
    cudaStreamWaitEvent(0, e2, 0);

    // Flash-fused QK^T + bias/mask + softmax + attn-out + AV
    fused_flash<<<dim3(NQ_/32, BH_), 256, FLASH_WORDS * 4>>>(
        Qh, Ql, Kh, Kl, Vp, biasw, attn, Ob);

    // Out projection
    mma_gemm<128,128,32,64,32,false,0,3><<<dim3(4,64,1),256>>>(
        Ob, Wo, bo, out, nullptr, nullptr, 512, 512, 512, 512, 0, 0, 0);
}

// round 13
// speedup vs baseline: 1.0474x; 1.0474x over previous
#include <cuda_runtime.h>
#include <cstdint>
#include <cstddef>
#include <math.h>

#define B_   8
#define NQ_  1024
#define NKV_ 1024
#define DQ_  512
#define H_   8
#define DH_  64
#define BH_  64

// Prepacked bf16 hi/lo operand arrays: [bh][n][32] u32 words
__device__ uint32_t g_Qh[BH_ * NQ_ * 32];
__device__ uint32_t g_Ql[BH_ * NQ_ * 32];
__device__ uint32_t g_Kh[BH_ * NKV_ * 32];
__device__ uint32_t g_Kl[BH_ * NKV_ * 32];
__device__ float    g_Vp[BH_ * NKV_ * DH_];   // fp32 [bh,k,d]
__device__ float    g_Obuf[B_ * NQ_ * H_ * DH_];
__device__ float    g_attn_scratch[(size_t)BH_ * NQ_ * NKV_];

__device__ __forceinline__ uint32_t packbf(float x0, float x1) {
    uint32_t r;
    asm("cvt.rn.bf16x2.f32 %0, %1, %2;" : "=r"(r) : "f"(x1), "f"(x0));
    return r;
}
__device__ __forceinline__ float bf_lo(uint32_t r) { return __uint_as_float(r << 16); }
__device__ __forceinline__ float bf_hi(uint32_t r) { return __uint_as_float(r & 0xffff0000u); }

__device__ __forceinline__ void mma16(float* c, const uint32_t* a, const uint32_t* b) {
    asm volatile(
        "mma.sync.aligned.m16n8k16.row.col.f32.bf16.bf16.f32 "
        "{%0,%1,%2,%3},{%4,%5,%6,%7},{%8,%9},{%0,%1,%2,%3};"
        : "+f"(c[0]), "+f"(c[1]), "+f"(c[2]), "+f"(c[3])
        : "r"(a[0]), "r"(a[1]), "r"(a[2]), "r"(a[3]), "r"(b[0]), "r"(b[1]));
}

__device__ __forceinline__ void cp16(uint32_t dst, const void* src) {
    asm volatile("cp.async.ca.shared.global [%0], [%1], 16;" :: "r"(dst), "l"(src));
}
#define CP_COMMIT() asm volatile("cp.async.commit_group;")
#define CP_WAIT0()  asm volatile("cp.async.wait_group 0;")
#define CP_WAIT1()  asm volatile("cp.async.wait_group 1;")

// ---------------------------------------------------------------------------
// Generic GEMM on bf16 tensor cores with split-bf16 accuracy.  (R8 verbatim)
// EPI: 0 store(+bias), 1 QKV fp32 scatter(+bias), 4 bf16x2 bias store,
//      5 QKV packed hi/lo scatter(+bias).
// ---------------------------------------------------------------------------
template <int BM, int BN, int BK, int WM, int WN, bool BCOL, int EPI, int NSPLIT,
          int MINBLK = 1, bool APACK = false>
__global__ __launch_bounds__(256, MINBLK) void mma_gemm(
    const float* __restrict__ A, const float* __restrict__ Bg,
    const float* __restrict__ bias, float* __restrict__ C,
    float* __restrict__ C2,
    int K, long lda, long ldb, long ldc, long sA, long sB, long sC)
{
    constexpr int MT = WM / 16, NT = WN / 8;
    constexpr int WX = BN / WN;
    constexpr int KW = BK / 2;
    constexpr bool SPL = (NSPLIT == 3);
    constexpr int BR  = BCOL ? BN : KW;
    constexpr int BCW = BCOL ? (KW + 4) : (BN + 8);

    __shared__ uint32_t sAh[BM][KW + 4];
    __shared__ uint32_t sAl[SPL ? BM : 1][SPL ? KW + 4 : 1];
    __shared__ uint32_t sBh[BR][BCW];
    __shared__ uint32_t sBl[SPL ? BR : 1][SPL ? BCW : 1];

    const int tid = threadIdx.x;
    const int warp = tid >> 5, lane = tid & 31;
    const int wx = warp % WX, wy = warp / WX;
    const long z = blockIdx.z;

    const float* Ab = APACK ? nullptr : (A + z * sA + (long)blockIdx.y * BM * lda);
    const uint32_t* Abw = APACK ? ((const uint32_t*)A + z * sA + (long)blockIdx.y * BM * lda)
                                : nullptr;
    const float* Bb = BCOL ? (Bg + z * sB + (long)blockIdx.x * BN * ldb)
                           : (Bg + z * sB + (long)blockIdx.x * BN);

    float acc[MT * NT][4];
#pragma unroll
    for (int i = 0; i < MT * NT; i++)
#pragma unroll
        for (int r = 0; r < 4; r++) acc[i][r] = 0.0f;

    for (int k0 = 0; k0 < K; k0 += BK) {
        if (APACK) {
            constexpr int TOT = BM * (KW / 4);
#pragma unroll
            for (int it = 0; it < (TOT + 255) / 256; it++) {
                int idx = tid + it * 256;
                if (TOT % 256 != 0 && idx >= TOT) break;
                int m = idx / (KW / 4), w4 = (idx % (KW / 4)) * 4;
                uint4 v = *(const uint4*)(Abw + (long)m * lda + (k0 >> 1) + w4);
                *(uint4*)&sAh[m][w4] = v;
            }
        } else {
            constexpr int AIT = (BM * BK / 4) / 256;
#pragma unroll
            for (int it = 0; it < AIT; it++) {
                int idx = tid + it * 256;
                int m = idx / (BK / 4), kq = idx % (BK / 4);
                float4 v = *(const float4*)(Ab + (long)m * lda + k0 + kq * 4);
                uint32_t h0 = packbf(v.x, v.y), h1 = packbf(v.z, v.w);
                sAh[m][kq * 2] = h0; sAh[m][kq * 2 + 1] = h1;
                if (SPL) {
                    sAl[m][kq * 2]     = packbf(v.x - bf_lo(h0), v.y - bf_hi(h0));
                    sAl[m][kq * 2 + 1] = packbf(v.z - bf_lo(h1), v.w - bf_hi(h1));
                }
            }
        }
        if (BCOL) {
            constexpr int BIT = (BN * BK / 4) / 256;
#pragma unroll
            for (int it = 0; it < BIT; it++) {
                int idx = tid + it * 256;
                int n = idx / (BK / 4), kq = idx % (BK / 4);
                float4 v = *(const float4*)(Bb + (long)n * ldb + k0 + kq * 4);
                uint32_t h0 = packbf(v.x, v.y), h1 = packbf(v.z, v.w);
                sBh[n][kq * 2] = h0; sBh[n][kq * 2 + 1] = h1;
                if (SPL) {
                    sBl[n][kq * 2]     = packbf(v.x - bf_lo(h0), v.y - bf_hi(h0));
                    sBl[n][kq * 2 + 1] = packbf(v.z - bf_lo(h1), v.w - bf_hi(h1));
                }
            }
        } else {
            constexpr int BIT = (KW * (BN / 4) + 255) / 256;
#pragma unroll
            for (int it = 0; it < BIT; it++) {
                int idx = tid + it * 256;
                if (KW * (BN / 4) % 256 != 0 && idx >= KW * (BN / 4)) break;
                int kp = idx / (BN / 4), n4 = (idx % (BN / 4)) * 4;
                float4 v0 = *(const float4*)(Bb + (long)(k0 + kp * 2) * ldb + n4);
                float4 v1 = *(const float4*)(Bb + (long)(k0 + kp * 2 + 1) * ldb + n4);
                uint32_t h0 = packbf(v0.x, v1.x), h1 = packbf(v0.y, v1.y);
                uint32_t h2 = packbf(v0.z, v1.z), h3 = packbf(v0.w, v1.w);
                sBh[kp][n4 + 0] = h0; sBh[kp][n4 + 1] = h1;
                sBh[kp][n4 + 2] = h2; sBh[kp][n4 + 3] = h3;
                if (SPL) {
                    sBl[kp][n4 + 0] = packbf(v0.x - bf_lo(h0), v1.x - bf_hi(h0));
                    sBl[kp][n4 + 1] = packbf(v0.y - bf_lo(h1), v1.y - bf_hi(h1));
                    sBl[kp][n4 + 2] = packbf(v0.z - bf_lo(h2), v1.z - bf_hi(h2));
                    sBl[kp][n4 + 3] = packbf(v0.w - bf_lo(h3), v1.w - bf_hi(h3));
                }
            }
        }
        __syncthreads();

#pragma unroll
        for (int kc = 0; kc < KW; kc += 8) {
            const int kb = kc + (lane & 3);
            const int mrow = wy * WM + (lane >> 2);
            uint32_t afh[MT][4], afl[MT][4];
#pragma unroll
            for (int i = 0; i < MT; i++) {
                int m = mrow + i * 16;
                afh[i][0] = sAh[m][kb];     afh[i][1] = sAh[m + 8][kb];
                afh[i][2] = sAh[m][kb + 4]; afh[i][3] = sAh[m + 8][kb + 4];
                if (SPL) {
                    afl[i][0] = sAl[m][kb];     afl[i][1] = sAl[m + 8][kb];
                    afl[i][2] = sAl[m][kb + 4]; afl[i][3] = sAl[m + 8][kb + 4];
                }
            }
#pragma unroll
            for (int j = 0; j < NT; j++) {
                uint32_t bfh[2], bfl[2];
                int n = wx * WN + j * 8 + (lane >> 2);
                if (BCOL) {
                    bfh[0] = sBh[n][kb]; bfh[1] = sBh[n][kb + 4];
                    if (SPL) { bfl[0] = sBl[n][kb]; bfl[1] = sBl[n][kb + 4]; }
                } else {
                    bfh[0] = sBh[kb][n]; bfh[1] = sBh[kb + 4][n];
                    if (SPL) { bfl[0] = sBl[kb][n]; bfl[1] = sBl[kb + 4][n]; }
                }
#pragma unroll
                for (int i = 0; i < MT; i++) {
                    mma16(acc[i * NT + j], afh[i], bfh);
                    if (SPL) {
                        mma16(acc[i * NT + j], afh[i], bfl);
                        mma16(acc[i * NT + j], afl[i], bfh);
                    }
                }
            }
        }
        __syncthreads();
    }

    const long m0 = (long)blockIdx.y * BM + wy * WM;
    const long n0 = (long)blockIdx.x * BN + wx * WN;
    float* Cb = C + z * sC;
    long ldcc = ldc;

#pragma unroll
    for (int i = 0; i < MT; i++) {
#pragma unroll
        for (int j = 0; j < NT; j++) {
#pragma unroll
            for (int r2 = 0; r2 < 2; r2++) {
                long row = m0 + i * 16 + r2 * 8 + (lane >> 2);
                long col = n0 + j * 8 + (lane & 3) * 2;
                float v0 = acc[i * NT + j][r2 * 2 + 0];
                float v1 = acc[i * NT + j][r2 * 2 + 1];
                if ((EPI == 0 || EPI == 1) && bias) { v0 += bias[col]; v1 += bias[col + 1]; }
                if (EPI == 1) {
                    long bb = row >> 10, ns = row & 1023;
                    long h = col >> 6, d = col & 63;
                    float* p = C + (((bb * 8 + h) * 1024 + ns) * 64 + d);
                    *(float2*)p = make_float2(v0, v1);
                } else if (EPI == 4) {
                    uint32_t* P = (uint32_t*)C;
                    __stcs(P + row * ldcc + z * sC + (col >> 1), packbf(v0, v1));
                } else if (EPI == 5) {
                    float w0 = v0 + (bias ? bias[col] : 0.0f);
                    float w1 = v1 + (bias ? bias[col + 1] : 0.0f);
                    uint32_t hw = packbf(w0, w1);
                    uint32_t lw = packbf(w0 - bf_lo(hw), w1 - bf_hi(hw));
                    long bb = row >> 10, ns = row & 1023;
                    long hh = col >> 6, d = col & 63;
                    long widx = ((bb * 8 + hh) * 1024 + ns) * 32 + (d >> 1);
                    ((uint32_t*)C)[widx]  = hw;
                    ((uint32_t*)C2)[widx] = lw;
                } else {
                    *(float2*)(Cb + row * ldcc + col) = make_float2(v0, v1);
                }
            }
        }
    }
}

// ---------------------------------------------------------------------------
// Fused attention (R8 structure) + Q fragments hoisted into registers.
// Grid (NQ/32, BH), 256 threads, 2-stage cp.async K pipeline.
// ---------------------------------------------------------------------------
#define FW_S   (32*1028)
#define FW_Q   (32*36)
#define FW_KST (128*36)
#define FUSED_WORDS (FW_S + 2*FW_Q + 4*FW_KST)

__global__ __launch_bounds__(256, 1) void fused_attn(
    const uint32_t* __restrict__ Qhw, const uint32_t* __restrict__ Qlw,
    const uint32_t* __restrict__ Khw, const uint32_t* __restrict__ Klw,
    const float* __restrict__ Vp, const int* __restrict__ mask,
    const uint32_t* __restrict__ biasw, float* __restrict__ attn,
    float* __restrict__ Obuf)
{
    extern __shared__ uint32_t sm[];
    float*    S    = (float*)sm;               // [32][1028] scores / packed P
    uint32_t* PS   = sm;
    uint32_t* sQh  = sm + FW_S;                // [32][36]
    uint32_t* sQl  = sQh + FW_Q;
    uint32_t* Kst  = sQl + FW_Q;               // 2 stages x (hi,lo) [128][36]
    const uint32_t stgb = (uint32_t)__cvta_generic_to_shared(Kst);

    const int tid = threadIdx.x, warp = tid >> 5, lane = tid & 31;
    const int q0 = blockIdx.x * 32, bh = blockIdx.y;
    const int b = bh >> 3, h = bh & 7;

    const uint32_t* QhB = Qhw + (size_t)bh * 32768 + q0 * 32;
    const uint32_t* QlB = Qlw + (size_t)bh * 32768 + q0 * 32;
    const uint32_t* KhB = Khw + (size_t)bh * 32768;
    const uint32_t* KlB = Klw + (size_t)bh * 32768;
    const float* Vb = Vp + (size_t)bh * 65536;
    float* attnb = attn + (size_t)bh * 1048576 + (size_t)q0 * 1024;
    const uint32_t* biasb = biasw + (size_t)bh * 524288 + (size_t)q0 * 512;

    // issue K tiles 0,1 into stages 0,1
#pragma unroll
    for (int s = 0; s < 2; s++) {
        uint32_t dH = stgb + (s * 2 * FW_KST) * 4;
        uint32_t dL = dH + FW_KST * 4;
        const uint32_t* sH = KhB + s * 128 * 32;
        const uint32_t* sL = KlB + s * 128 * 32;
#pragma unroll
        for (int c = 0; c < 4; c++) {
            int f = tid + c * 256;
            int r = f >> 3, ch = (f & 7) * 4;
            cp16(dH + (r * 36 + ch) * 4, sH + r * 32 + ch);
            cp16(dL + (r * 36 + ch) * 4, sL + r * 32 + ch);
        }
        CP_COMMIT();
    }

    // stage Q (prepacked)
    {
        int m = tid >> 3, w = (tid & 7) * 4;
        *(uint4*)&sQh[m * 36 + w] = *(const uint4*)(QhB + m * 32 + w);
        *(uint4*)&sQl[m * 36 + w] = *(const uint4*)(QlB + m * 32 + w);
    }
    __syncthreads();

    // Hoist Q fragments into registers ONCE (loop-invariant; barriers
    // otherwise prevent ptxas from hoisting these LDS out of the kt loop).
    uint32_t qfh[2][4][4], qfl[2][4][4];   // [mi][c][frag]
    {
        const int lc = lane & 3, r4 = lane >> 2;
#pragma unroll
        for (int c = 0; c < 4; c++) {
            int kb = c * 8 + lc;
#pragma unroll
            for (int mi = 0; mi < 2; mi++) {
                int m = mi * 16 + r4;
                qfh[mi][c][0] = sQh[m * 36 + kb];     qfh[mi][c][1] = sQh[(m + 8) * 36 + kb];
                qfh[mi][c][2] = sQh[m * 36 + kb + 4]; qfh[mi][c][3] = sQh[(m + 8) * 36 + kb + 4];
                qfl[mi][c][0] = sQl[m * 36 + kb];     qfl[mi][c][1] = sQl[(m + 8) * 36 + kb];
                qfl[mi][c][2] = sQl[m * 36 + kb + 4]; qfl[mi][c][3] = sQl[(m + 8) * 36 + kb + 4];
            }
        }
    }

    // ---- phase 1: S = Q K^T (split bf16), 2-stage cp.async pipeline ----
    for (int kt = 0; kt < 8; kt++) {
        if (kt < 7) { CP_WAIT1(); } else { CP_WAIT0(); }
        __syncthreads();
        const uint32_t* bKh = Kst + (kt & 1) * 2 * FW_KST;
        const uint32_t* bKl = bKh + FW_KST;
        float acc[2][2][4] = {};
#pragma unroll
        for (int c = 0; c < 4; c++) {
            int kb = c * 8 + (lane & 3);
#pragma unroll
            for (int nj = 0; nj < 2; nj++) {
                int n = warp * 16 + nj * 8 + (lane >> 2);
                uint32_t bfh[2] = { bKh[n * 36 + kb], bKh[n * 36 + kb + 4] };
                uint32_t bfl[2] = { bKl[n * 36 + kb], bKl[n * 36 + kb + 4] };
#pragma unroll
                for (int mi = 0; mi < 2; mi++) {
                    mma16(acc[mi][nj], qfh[mi][c], bfh);
                    mma16(acc[mi][nj], qfh[mi][c], bfl);
                    mma16(acc[mi][nj], qfl[mi][c], bfh);
                }
            }
        }
#pragma unroll
        for (int mi = 0; mi < 2; mi++)
#pragma unroll
            for (int nj = 0; nj < 2; nj++) {
                int r = mi * 16 + (lane >> 2);
                int cc = kt * 128 + warp * 16 + nj * 8 + (lane & 3) * 2;
                *(float2*)&S[r * 1028 + cc]       = make_float2(acc[mi][nj][0], acc[mi][nj][1]);
                *(float2*)&S[(r + 8) * 1028 + cc] = make_float2(acc[mi][nj][2], acc[mi][nj][3]);
            }
        __syncthreads();
        if (kt + 2 < 8) {
            int s = kt & 1;
            uint32_t dH = stgb + (s * 2 * FW_KST) * 4;
            uint32_t dL = dH + FW_KST * 4;
            const uint32_t* sH = KhB + (kt + 2) * 128 * 32;
            const uint32_t* sL = KlB + (kt + 2) * 128 * 32;
#pragma unroll
            for (int c = 0; c < 4; c++) {
                int f = tid + c * 256;
                int r = f >> 3, ch = (f & 7) * 4;
                cp16(dH + (r * 36 + ch) * 4, sH + r * 32 + ch);
                cp16(dL + (r * 36 + ch) * 4, sL + r * 32 + ch);
            }
            CP_COMMIT();
        }
    }

    // ---- phase 2: softmax((S + bias)*scale, mask) -> attn + packed P ----
    const int4* mrow = (const int4*)(mask + b * 1024);
    for (int rr = 0; rr < 4; rr++) {
        int r = warp * 4 + rr;
        float4 v[8];
        float mx = -INFINITY;
#pragma unroll
        for (int j = 0; j < 8; j++) {
            int c4 = lane + j * 32;
            float4 s4 = *(float4*)&S[r * 1028 + c4 * 4];
            uint2 bw = __ldcs((const uint2*)(biasb + (size_t)r * 512 + c4 * 2));
            int4 mm = mrow[c4];
            s4.x = mm.x ? (s4.x + bf_lo(bw.x)) * 0.125f : -INFINITY;
            s4.y = mm.y ? (s4.y + bf_hi(bw.x)) * 0.125f : -INFINITY;
            s4.z = mm.z ? (s4.z + bf_lo(bw.y)) * 0.125f : -INFINITY;
            s4.w = mm.w ? (s4.w + bf_hi(bw.y)) * 0.125f : -INFINITY;
            v[j] = s4;
            mx = fmaxf(mx, fmaxf(fmaxf(s4.x, s4.y), fmaxf(s4.z, s4.w)));
        }
#pragma unroll
        for (int o = 16; o; o >>= 1) mx = fmaxf(mx, __shfl_xor_sync(0xffffffffu, mx, o));
        float sum = 0.0f;
#pragma unroll
        for (int j = 0; j < 8; j++) {
            v[j].x = __expf(v[j].x - mx); v[j].y = __expf(v[j].y - mx);
            v[j].z = __expf(v[j].z - mx); v[j].w = __expf(v[j].w - mx);
            sum += v[j].x + v[j].y + v[j].z + v[j].w;
        }
#pragma unroll
        for (int o = 16; o; o >>= 1) sum += __shfl_xor_sync(0xffffffffu, sum, o);
        float inv = 1.0f / sum;
#pragma unroll
        for (int j = 0; j < 8; j++) {
            v[j].x *= inv; v[j].y *= inv; v[j].z *= inv; v[j].w *= inv;
            int c4 = lane + j * 32;
            __stcs((float4*)(attnb + (size_t)r * 1024 + c4 * 4), v[j]);
            uint32_t h0 = packbf(v[j].x, v[j].y), h1 = packbf(v[j].z, v[j].w);
            PS[r * 1028 + c4 * 2]     = h0;
            PS[r * 1028 + c4 * 2 + 1] = h1;
            PS[r * 1028 + 514 + c4 * 2]     = packbf(v[j].x - bf_lo(h0), v[j].y - bf_hi(h0));
            PS[r * 1028 + 514 + c4 * 2 + 1] = packbf(v[j].z - bf_lo(h1), v[j].w - bf_hi(h1));
        }
    }
    __syncthreads();

    // ---- phase 3: O = P V (split bf16), V fp32 streamed; operands in stage0 ----
    uint32_t* KVh = Kst;             // [64][68]
    uint32_t* KVl = Kst + FW_KST;
    float accO[2][4] = {};
    for (int kt = 0; kt < 8; kt++) {
#pragma unroll
        for (int t = 0; t < 4; t++) {
            int f = tid + t * 256;
            int p = f >> 4, d4 = (f & 15) * 4;
            const float* vp0 = Vb + (kt * 128 + 2 * p) * 64 + d4;
            float4 v0 = *(const float4*)vp0;
            float4 v1 = *(const float4*)(vp0 + 64);
            uint32_t w0 = packbf(v0.x, v1.x), w1 = packbf(v0.y, v1.y);
            uint32_t w2 = packbf(v0.z, v1.z), w3 = packbf(v0.w, v1.w);
            KVh[(d4 + 0) * 68 + p] = w0; KVh[(d4 + 1) * 68 + p] = w1;
            KVh[(d4 + 2) * 68 + p] = w2; KVh[(d4 + 3) * 68 + p] = w3;
            KVl[(d4 + 0) * 68 + p] = packbf(v0.x - bf_lo(w0), v1.x - bf_hi(w0));
            KVl[(d4 + 1) * 68 + p] = packbf(v0.y - bf_lo(w1), v1.y - bf_hi(w1));
            KVl[(d4 + 2) * 68 + p] = packbf(v0.z - bf_lo(w2), v1.z - bf_hi(w2));
            KVl[(d4 + 3) * 68 + p] = packbf(v0.w - bf_lo(w3), v1.w - bf_hi(w3));
        }
        __syncthreads();
#pragma unroll
        for (int c = 0; c < 8; c++) {
            int kb = c * 8 + (lane & 3);
            int gk = kt * 64 + kb;
            uint32_t ah[2][4], al[2][4];
#pragma unroll
            for (int mi = 0; mi < 2; mi++) {
                int m = mi * 16 + (lane >> 2);
                ah[mi][0] = PS[m * 1028 + gk];           ah[mi][1] = PS[(m + 8) * 1028 + gk];
                ah[mi][2] = PS[m * 1028 + gk + 4];       ah[mi][3] = PS[(m + 8) * 1028 + gk + 4];
                al[mi][0] = PS[m * 1028 + 514 + gk];     al[mi][1] = PS[(m + 8) * 1028 + 514 + gk];
                al[mi][2] = PS[m * 1028 + 514 + gk + 4]; al[mi][3] = PS[(m + 8) * 1028 + 514 + gk + 4];
            }
            int n = warp * 8 + (lane >> 2);
            uint32_t bvh[2] = { KVh[n * 68 + kb], KVh[n * 68 + kb + 4] };
            uint32_t bvl[2] = { KVl[n * 68 + kb], KVl[n * 68 + kb + 4] };
#pragma unroll
            for (int mi = 0; mi < 2; mi++) {
                mma16(accO[mi], ah[mi], bvh);
                mma16(accO[mi], ah[mi], bvl);
                mma16(accO[mi], al[mi], bvh);
            }
        }
        __syncthreads();
    }
#pragma unroll
    for (int mi = 0; mi < 2; mi++) {
        int r0 = q0 + mi * 16 + (lane >> 2);
        int col = h * 64 + warp * 8 + (lane & 3) * 2;
        *(float2*)&Obuf[(size_t)(b * 1024 + r0) * 512 + col]     = make_float2(accO[mi][0], accO[mi][1]);
        *(float2*)&Obuf[(size_t)(b * 1024 + r0 + 8) * 512 + col] = make_float2(accO[mi][2], accO[mi][3]);
    }
}

// ---------------------------------------------------------------------------
extern "C" void kernel_launch(void* const* d_in, const int* in_sizes, int n_in,
                              void* d_out, int out_size)
{
    const float* q    = (const float*)d_in[0];
    const float* kv   = (const float*)d_in[1];
    const int*   mask = (const int*)d_in[2];
    const float* Wq   = (const float*)d_in[3];
    const float* bq   = (const float*)d_in[4];
    const float* Wk   = (const float*)d_in[5];
    const float* bk   = (const float*)d_in[6];
    const float* Wv   = (const float*)d_in[7];
    const float* bv   = (const float*)d_in[8];
    const float* Wo   = (const float*)d_in[9];
    const float* bo   = (const float*)d_in[10];
    const float* R    = (const float*)d_in[11];

    float* out = (float*)d_out;
    const size_t OUT0_ELEMS = (size_t)B_ * NQ_ * DQ_;
    const size_t ATTN_ELEMS = (size_t)BH_ * NQ_ * NKV_;

    uint32_t *Qh, *Ql, *Kh, *Kl;
    float *Vp, *Ob, *scr;
    cudaGetSymbolAddress((void**)&Qh, g_Qh);
    cudaGetSymbolAddress((void**)&Ql, g_Ql);
    cudaGetSymbolAddress((void**)&Kh, g_Kh);
    cudaGetSymbolAddress((void**)&Kl, g_Kl);
    cudaGetSymbolAddress((void**)&Vp, g_Vp);
    cudaGetSymbolAddress((void**)&Ob, g_Obuf);
    cudaGetSymbolAddress((void**)&scr, g_attn_scratch);

    float* attn = ((size_t)out_size >= OUT0_ELEMS + ATTN_ELEMS) ? (out + OUT0_ELEMS)
                                                                : scr + ATTN_ELEMS / 2;
    uint32_t* biasw = (uint32_t*)scr;

    static cudaStream_t s1 = nullptr, s2 = nullptr;
    static cudaEvent_t eRoot, e1, e2;
    static int init_done = 0;
    if (!init_done) {
        cudaFuncSetAttribute(fused_attn, cudaFuncAttributeMaxDynamicSharedMemorySize,
                             FUSED_WORDS * 4);
        cudaStreamCreateWithFlags(&s1, cudaStreamNonBlocking);
        cudaStreamCreateWithFlags(&s2, cudaStreamNonBlocking);
        cudaEventCreateWithFlags(&eRoot, cudaEventDisableTiming);
        cudaEventCreateWithFlags(&e1, cudaEventDisableTiming);
        cudaEventCreateWithFlags(&e2, cudaEventDisableTiming);
        init_done = 1;
    }

    cudaEventRecord(eRoot, 0);
    cudaStreamWaitEvent(s1, eRoot, 0);
    cudaStreamWaitEvent(s2, eRoot, 0);

    // K projection -> packed hi/lo  (side stream)
    mma_gemm<128,128,32,64,32,false,5,3><<<dim3(4,64,1),256,0,s1>>>(
        kv, Wk, bk, (float*)Kh, (float*)Kl, 512, 512, 512, 0, 0, 0, 0);
    // V projection -> fp32 scatter  (side stream)
    mma_gemm<128,128,32,64,32,false,1,3><<<dim3(4,64,1),256,0,s2>>>(
        kv, Wv, bv, Vp, nullptr, 512, 512, 512, 0, 0, 0, 0);

    // Q projection -> packed hi/lo  (main stream)
    mma_gemm<128,128,32,64,32,false,5,3><<<dim3(4,64,1),256>>>(
        q, Wq, bq, (float*)Qh, (float*)Ql, 512, 512, 512, 0, 0, 0, 0);

    // RPE bias from prepacked Q hi (APACK, NSPLIT=1, MINBLK=4)
    mma_gemm<64,128,32,32,32,true,4,1,4,true><<<dim3(8,1,1024),256>>>(
        (const float*)Qh, R, nullptr, (float*)biasw, nullptr, 64,
        /*lda(words)=*/32768, /*ldb=*/64, /*ldc=*/524288,
        /*sA(words)=*/32, /*sB=*/65536, /*sC=*/512);

    cudaEventRecord(e1, s1);
    cudaEventRecord(e2, s2);
    cudaStreamWaitEvent(0, e1, 0);
    cudaStreamWaitEvent(0, e2, 0);

    // Fused QK^T + bias + mask/scale + softmax + AV
    fused_attn<<<dim3(NQ_/32, BH_), 256, FUSED_WORDS * 4>>>(
        Qh, Ql, Kh, Kl, Vp, mask, biasw, attn, Ob);

    // Out projection
    mma_gemm<128,128,32,64,32,false,0,3><<<dim3(4,64,1),256>>>(
        Ob, Wo, bo, out, nullptr, 512, 512, 512, 512, 0, 0, 0);
}

// round 15
// speedup vs baseline: 1.0528x; 1.0052x over previous
#include <cuda_runtime.h>
#include <cstdint>
#include <cstddef>
#include <math.h>

#define B_   8
#define NQ_  1024
#define NKV_ 1024
#define DQ_  512
#define H_   8
#define DH_  64
#define BH_  64

// Prepacked bf16 hi/lo operand arrays: [bh][n][32] u32 words
__device__ uint32_t g_Qh[BH_ * NQ_ * 32];
__device__ uint32_t g_Ql[BH_ * NQ_ * 32];
__device__ uint32_t g_Kh[BH_ * NKV_ * 32];
__device__ uint32_t g_Kl[BH_ * NKV_ * 32];
__device__ float    g_Vp[BH_ * NKV_ * DH_];   // fp32 [bh,k,d]
__device__ float    g_Obuf[B_ * NQ_ * H_ * DH_];
__device__ float    g_attn_scratch[(size_t)BH_ * NQ_ * NKV_];

__device__ __forceinline__ uint32_t packbf(float x0, float x1) {
    uint32_t r;
    asm("cvt.rn.bf16x2.f32 %0, %1, %2;" : "=r"(r) : "f"(x1), "f"(x0));
    return r;
}
__device__ __forceinline__ float bf_lo(uint32_t r) { return __uint_as_float(r << 16); }
__device__ __forceinline__ float bf_hi(uint32_t r) { return __uint_as_float(r & 0xffff0000u); }

__device__ __forceinline__ void mma16(float* c, const uint32_t* a, const uint32_t* b) {
    asm volatile(
        "mma.sync.aligned.m16n8k16.row.col.f32.bf16.bf16.f32 "
        "{%0,%1,%2,%3},{%4,%5,%6,%7},{%8,%9},{%0,%1,%2,%3};"
        : "+f"(c[0]), "+f"(c[1]), "+f"(c[2]), "+f"(c[3])
        : "r"(a[0]), "r"(a[1]), "r"(a[2]), "r"(a[3]), "r"(b[0]), "r"(b[1]));
}

__device__ __forceinline__ void ldsm4(uint32_t* r, uint32_t addr) {
    asm volatile("ldmatrix.sync.aligned.m8n8.x4.shared.b16 {%0,%1,%2,%3}, [%4];"
        : "=r"(r[0]), "=r"(r[1]), "=r"(r[2]), "=r"(r[3]) : "r"(addr));
}

__device__ __forceinline__ void cp16(uint32_t dst, const void* src) {
    asm volatile("cp.async.ca.shared.global [%0], [%1], 16;" :: "r"(dst), "l"(src));
}
#define CP_COMMIT() asm volatile("cp.async.commit_group;")
#define CP_WAIT0()  asm volatile("cp.async.wait_group 0;")
#define CP_WAIT1()  asm volatile("cp.async.wait_group 1;")

// ---------------------------------------------------------------------------
// Generic GEMM on bf16 tensor cores with split-bf16 accuracy.  (R8 verbatim)
// ---------------------------------------------------------------------------
template <int BM, int BN, int BK, int WM, int WN, bool BCOL, int EPI, int NSPLIT,
          int MINBLK = 1, bool APACK = false>
__global__ __launch_bounds__(256, MINBLK) void mma_gemm(
    const float* __restrict__ A, const float* __restrict__ Bg,
    const float* __restrict__ bias, float* __restrict__ C,
    float* __restrict__ C2,
    int K, long lda, long ldb, long ldc, long sA, long sB, long sC)
{
    constexpr int MT = WM / 16, NT = WN / 8;
    constexpr int WX = BN / WN;
    constexpr int KW = BK / 2;
    constexpr bool SPL = (NSPLIT == 3);
    constexpr int BR  = BCOL ? BN : KW;
    constexpr int BCW = BCOL ? (KW + 4) : (BN + 8);

    __shared__ uint32_t sAh[BM][KW + 4];
    __shared__ uint32_t sAl[SPL ? BM : 1][SPL ? KW + 4 : 1];
    __shared__ uint32_t sBh[BR][BCW];
    __shared__ uint32_t sBl[SPL ? BR : 1][SPL ? BCW : 1];

    const int tid = threadIdx.x;
    const int warp = tid >> 5, lane = tid & 31;
    const int wx = warp % WX, wy = warp / WX;
    const long z = blockIdx.z;

    const float* Ab = APACK ? nullptr : (A + z * sA + (long)blockIdx.y * BM * lda);
    const uint32_t* Abw = APACK ? ((const uint32_t*)A + z * sA + (long)blockIdx.y * BM * lda)
                                : nullptr;
    const float* Bb = BCOL ? (Bg + z * sB + (long)blockIdx.x * BN * ldb)
                           : (Bg + z * sB + (long)blockIdx.x * BN);

    float acc[MT * NT][4];
#pragma unroll
    for (int i = 0; i < MT * NT; i++)
#pragma unroll
        for (int r = 0; r < 4; r++) acc[i][r] = 0.0f;

    for (int k0 = 0; k0 < K; k0 += BK) {
        if (APACK) {
            constexpr int TOT = BM * (KW / 4);
#pragma unroll
            for (int it = 0; it < (TOT + 255) / 256; it++) {
                int idx = tid + it * 256;
                if (TOT % 256 != 0 && idx >= TOT) break;
                int m = idx / (KW / 4), w4 = (idx % (KW / 4)) * 4;
                uint4 v = *(const uint4*)(Abw + (long)m * lda + (k0 >> 1) + w4);
                *(uint4*)&sAh[m][w4] = v;
            }
        } else {
            constexpr int AIT = (BM * BK / 4) / 256;
#pragma unroll
            for (int it = 0; it < AIT; it++) {
                int idx = tid + it * 256;
                int m = idx / (BK / 4), kq = idx % (BK / 4);
                float4 v = *(const float4*)(Ab + (long)m * lda + k0 + kq * 4);
                uint32_t h0 = packbf(v.x, v.y), h1 = packbf(v.z, v.w);
                sAh[m][kq * 2] = h0; sAh[m][kq * 2 + 1] = h1;
                if (SPL) {
                    sAl[m][kq * 2]     = packbf(v.x - bf_lo(h0), v.y - bf_hi(h0));
                    sAl[m][kq * 2 + 1] = packbf(v.z - bf_lo(h1), v.w - bf_hi(h1));
                }
            }
        }
        if (BCOL) {
            constexpr int BIT = (BN * BK / 4) / 256;
#pragma unroll
            for (int it = 0; it < BIT; it++) {
                int idx = tid + it * 256;
                int n = idx / (BK / 4), kq = idx % (BK / 4);
                float4 v = *(const float4*)(Bb + (long)n * ldb + k0 + kq * 4);
                uint32_t h0 = packbf(v.x, v.y), h1 = packbf(v.z, v.w);
                sBh[n][kq * 2] = h0; sBh[n][kq * 2 + 1] = h1;
                if (SPL) {
                    sBl[n][kq * 2]     = packbf(v.x - bf_lo(h0), v.y - bf_hi(h0));
                    sBl[n][kq * 2 + 1] = packbf(v.z - bf_lo(h1), v.w - bf_hi(h1));
                }
            }
        } else {
            constexpr int BIT = (KW * (BN / 4) + 255) / 256;
#pragma unroll
            for (int it = 0; it < BIT; it++) {
                int idx = tid + it * 256;
                if (KW * (BN / 4) % 256 != 0 && idx >= KW * (BN / 4)) break;
                int kp = idx / (BN / 4), n4 = (idx % (BN / 4)) * 4;
                float4 v0 = *(const float4*)(Bb + (long)(k0 + kp * 2) * ldb + n4);
                float4 v1 = *(const float4*)(Bb + (long)(k0 + kp * 2 + 1) * ldb + n4);
                uint32_t h0 = packbf(v0.x, v1.x), h1 = packbf(v0.y, v1.y);
                uint32_t h2 = packbf(v0.z, v1.z), h3 = packbf(v0.w, v1.w);
                sBh[kp][n4 + 0] = h0; sBh[kp][n4 + 1] = h1;
                sBh[kp][n4 + 2] = h2; sBh[kp][n4 + 3] = h3;
                if (SPL) {
                    sBl[kp][n4 + 0] = packbf(v0.x - bf_lo(h0), v1.x - bf_hi(h0));
                    sBl[kp][n4 + 1] = packbf(v0.y - bf_lo(h1), v1.y - bf_hi(h1));
                    sBl[kp][n4 + 2] = packbf(v0.z - bf_lo(h2), v1.z - bf_hi(h2));
                    sBl[kp][n4 + 3] = packbf(v0.w - bf_lo(h3), v1.w - bf_hi(h3));
                }
            }
        }
        __syncthreads();

#pragma unroll
        for (int kc = 0; kc < KW; kc += 8) {
            const int kb = kc + (lane & 3);
            const int mrow = wy * WM + (lane >> 2);
            uint32_t afh[MT][4], afl[MT][4];
#pragma unroll
            for (int i = 0; i < MT; i++) {
                int m = mrow + i * 16;
                afh[i][0] = sAh[m][kb];     afh[i][1] = sAh[m + 8][kb];
                afh[i][2] = sAh[m][kb + 4]; afh[i][3] = sAh[m + 8][kb + 4];
                if (SPL) {
                    afl[i][0] = sAl[m][kb];     afl[i][1] = sAl[m + 8][kb];
                    afl[i][2] = sAl[m][kb + 4]; afl[i][3] = sAl[m + 8][kb + 4];
                }
            }
#pragma unroll
            for (int j = 0; j < NT; j++) {
                uint32_t bfh[2], bfl[2];
                int n = wx * WN + j * 8 + (lane >> 2);
                if (BCOL) {
                    bfh[0] = sBh[n][kb]; bfh[1] = sBh[n][kb + 4];
                    if (SPL) { bfl[0] = sBl[n][kb]; bfl[1] = sBl[n][kb + 4]; }
                } else {
                    bfh[0] = sBh[kb][n]; bfh[1] = sBh[kb + 4][n];
                    if (SPL) { bfl[0] = sBl[kb][n]; bfl[1] = sBl[kb + 4][n]; }
                }
#pragma unroll
                for (int i = 0; i < MT; i++) {
                    mma16(acc[i * NT + j], afh[i], bfh);
                    if (SPL) {
                        mma16(acc[i * NT + j], afh[i], bfl);
                        mma16(acc[i * NT + j], afl[i], bfh);
                    }
                }
            }
        }
        __syncthreads();
    }

    const long m0 = (long)blockIdx.y * BM + wy * WM;
    const long n0 = (long)blockIdx.x * BN + wx * WN;
    float* Cb = C + z * sC;
    long ldcc = ldc;

#pragma unroll
    for (int i = 0; i < MT; i++) {
#pragma unroll
        for (int j = 0; j < NT; j++) {
#pragma unroll
            for (int r2 = 0; r2 < 2; r2++) {
                long row = m0 + i * 16 + r2 * 8 + (lane >> 2);
                long col = n0 + j * 8 + (lane & 3) * 2;
                float v0 = acc[i * NT + j][r2 * 2 + 0];
                float v1 = acc[i * NT + j][r2 * 2 + 1];
                if ((EPI == 0 || EPI == 1) && bias) { v0 += bias[col]; v1 += bias[col + 1]; }
                if (EPI == 1) {
                    long bb = row >> 10, ns = row & 1023;
                    long h = col >> 6, d = col & 63;
                    float* p = C + (((bb * 8 + h) * 1024 + ns) * 64 + d);
                    *(float2*)p = make_float2(v0, v1);
                } else if (EPI == 4) {
                    uint32_t* P = (uint32_t*)C;
                    __stcs(P + row * ldcc + z * sC + (col >> 1), packbf(v0, v1));
                } else if (EPI == 5) {
                    float w0 = v0 + (bias ? bias[col] : 0.0f);
                    float w1 = v1 + (bias ? bias[col + 1] : 0.0f);
                    uint32_t hw = packbf(w0, w1);
                    uint32_t lw = packbf(w0 - bf_lo(hw), w1 - bf_hi(hw));
                    long bb = row >> 10, ns = row & 1023;
                    long hh = col >> 6, d = col & 63;
                    long widx = ((bb * 8 + hh) * 1024 + ns) * 32 + (d >> 1);
                    ((uint32_t*)C)[widx]  = hw;
                    ((uint32_t*)C2)[widx] = lw;
                } else {
                    *(float2*)(Cb + row * ldcc + col) = make_float2(v0, v1);
                }
            }
        }
    }
}

// Marker: aligns fused_attn onto ncu's fixed `-s 5` launch index.
__global__ void marker_kernel() {}

// ---------------------------------------------------------------------------
// Fused attention: R13 numerics (full split-bf16 AV) + LDSM fragment loads.
// Grid (NQ/32, BH), 256 threads, 2-stage cp.async K pipeline.
// ---------------------------------------------------------------------------
#define FW_S   (32*1028)
#define FW_Q   (32*36)
#define FW_KST (128*36)
#define FUSED_WORDS (FW_S + 2*FW_Q + 4*FW_KST)

__global__ __launch_bounds__(256, 1) void fused_attn(
    const uint32_t* __restrict__ Qhw, const uint32_t* __restrict__ Qlw,
    const uint32_t* __restrict__ Khw, const uint32_t* __restrict__ Klw,
    const float* __restrict__ Vp, const int* __restrict__ mask,
    const uint32_t* __restrict__ biasw, float* __restrict__ attn,
    float* __restrict__ Obuf)
{
    extern __shared__ uint32_t sm[];
    float*    S    = (float*)sm;               // [32][1028] scores / packed P
    uint32_t* PS   = sm;                       // P hi at row+0, lo at row+512
    uint32_t* sQh  = sm + FW_S;                // [32][36]
    uint32_t* sQl  = sQh + FW_Q;
    uint32_t* Kst  = sQl + FW_Q;               // 2 stages x (hi,lo) [128][36]
    const uint32_t psb  = (uint32_t)__cvta_generic_to_shared(sm);
    const uint32_t stgb = (uint32_t)__cvta_generic_to_shared(Kst);

    const int tid = threadIdx.x, warp = tid >> 5, lane = tid & 31;
    const int q0 = blockIdx.x * 32, bh = blockIdx.y;
    const int b = bh >> 3, h = bh & 7;

    const uint32_t* QhB = Qhw + (size_t)bh * 32768 + q0 * 32;
    const uint32_t* QlB = Qlw + (size_t)bh * 32768 + q0 * 32;
    const uint32_t* KhB = Khw + (size_t)bh * 32768;
    const uint32_t* KlB = Klw + (size_t)bh * 32768;
    const float* Vb = Vp + (size_t)bh * 65536;
    float* attnb = attn + (size_t)bh * 1048576 + (size_t)q0 * 1024;
    const uint32_t* biasb = biasw + (size_t)bh * 524288 + (size_t)q0 * 512;

    // issue K tiles 0,1 into stages 0,1
#pragma unroll
    for (int s = 0; s < 2; s++) {
        uint32_t dH = stgb + (s * 2 * FW_KST) * 4;
        uint32_t dL = dH + FW_KST * 4;
        const uint32_t* sH = KhB + s * 128 * 32;
        const uint32_t* sL = KlB + s * 128 * 32;
#pragma unroll
        for (int c = 0; c < 4; c++) {
            int f = tid + c * 256;
            int r = f >> 3, ch = (f & 7) * 4;
            cp16(dH + (r * 36 + ch) * 4, sH + r * 32 + ch);
            cp16(dL + (r * 36 + ch) * 4, sL + r * 32 + ch);
        }
        CP_COMMIT();
    }

    // stage Q (prepacked)
    {
        int m = tid >> 3, w = (tid & 7) * 4;
        *(uint4*)&sQh[m * 36 + w] = *(const uint4*)(QhB + m * 32 + w);
        *(uint4*)&sQl[m * 36 + w] = *(const uint4*)(QlB + m * 32 + w);
    }
    __syncthreads();

    // Hoist Q fragments into registers ONCE (R13 win).
    uint32_t qfh[2][4][4], qfl[2][4][4];
    {
        const int lc = lane & 3, r4 = lane >> 2;
#pragma unroll
        for (int c = 0; c < 4; c++) {
            int kb = c * 8 + lc;
#pragma unroll
            for (int mi = 0; mi < 2; mi++) {
                int m = mi * 16 + r4;
                qfh[mi][c][0] = sQh[m * 36 + kb];     qfh[mi][c][1] = sQh[(m + 8) * 36 + kb];
                qfh[mi][c][2] = sQh[m * 36 + kb + 4]; qfh[mi][c][3] = sQh[(m + 8) * 36 + kb + 4];
                qfl[mi][c][0] = sQl[m * 36 + kb];     qfl[mi][c][1] = sQl[(m + 8) * 36 + kb];
                qfl[mi][c][2] = sQl[m * 36 + kb + 4]; qfl[mi][c][3] = sQl[(m + 8) * 36 + kb + 4];
            }
        }
    }

    const int lt = lane >> 3, lr = lane & 7;   // ldmatrix lane decomposition

    // ---- phase 1: S = Q K^T (split bf16); K fragments via LDSM x4 ----
    for (int kt = 0; kt < 8; kt++) {
        if (kt < 7) { CP_WAIT1(); } else { CP_WAIT0(); }
        __syncthreads();
        const uint32_t kbase = stgb + ((kt & 1) * 2 * FW_KST) * 4;
        float acc[2][2][4] = {};
#pragma unroll
        for (int c = 0; c < 4; c++) {
            // tiles: [nj0ch0, nj0ch1, nj1ch0, nj1ch1]
            uint32_t bfh[4], bfl[4];
            uint32_t kaddr = kbase +
                ((warp * 16 + (lt >> 1) * 8 + lr) * 36 + c * 8 + (lt & 1) * 4) * 4;
            ldsm4(bfh, kaddr);
            ldsm4(bfl, kaddr + FW_KST * 4);
#pragma unroll
            for (int mi = 0; mi < 2; mi++) {
                mma16(acc[mi][0], qfh[mi][c], &bfh[0]);
                mma16(acc[mi][0], qfh[mi][c], &bfl[0]);
                mma16(acc[mi][0], qfl[mi][c], &bfh[0]);
                mma16(acc[mi][1], qfh[mi][c], &bfh[2]);
                mma16(acc[mi][1], qfh[mi][c], &bfl[2]);
                mma16(acc[mi][1], qfl[mi][c], &bfh[2]);
            }
        }
#pragma unroll
        for (int mi = 0; mi < 2; mi++)
#pragma unroll
            for (int nj = 0; nj < 2; nj++) {
                int r = mi * 16 + (lane >> 2);
                int cc = kt * 128 + warp * 16 + nj * 8 + (lane & 3) * 2;
                *(float2*)&S[r * 1028 + cc]       = make_float2(acc[mi][nj][0], acc[mi][nj][1]);
                *(float2*)&S[(r + 8) * 1028 + cc] = make_float2(acc[mi][nj][2], acc[mi][nj][3]);
            }
        __syncthreads();
        if (kt + 2 < 8) {
            int s = kt & 1;
            uint32_t dH = stgb + (s * 2 * FW_KST) * 4;
            uint32_t dL = dH + FW_KST * 4;
            const uint32_t* sH = KhB + (kt + 2) * 128 * 32;
            const uint32_t* sL = KlB + (kt + 2) * 128 * 32;
#pragma unroll
            for (int c = 0; c < 4; c++) {
                int f = tid + c * 256;
                int r = f >> 3, ch = (f & 7) * 4;
                cp16(dH + (r * 36 + ch) * 4, sH + r * 32 + ch);
                cp16(dL + (r * 36 + ch) * 4, sL + r * 32 + ch);
            }
            CP_COMMIT();
        }
    }

    // ---- phase 2: softmax -> attn + packed P (hi at +0, lo at +512) ----
    const int4* mrow = (const int4*)(mask + b * 1024);
    for (int rr = 0; rr < 4; rr++) {
        int r = warp * 4 + rr;
        float4 v[8];
        float mx = -INFINITY;
#pragma unroll
        for (int j = 0; j < 8; j++) {
            int c4 = lane + j * 32;
            float4 s4 = *(float4*)&S[r * 1028 + c4 * 4];
            uint2 bw = __ldcs((const uint2*)(biasb + (size_t)r * 512 + c4 * 2));
            int4 mm = mrow[c4];
            s4.x = mm.x ? (s4.x + bf_lo(bw.x)) * 0.125f : -INFINITY;
            s4.y = mm.y ? (s4.y + bf_hi(bw.x)) * 0.125f : -INFINITY;
            s4.z = mm.z ? (s4.z + bf_lo(bw.y)) * 0.125f : -INFINITY;
            s4.w = mm.w ? (s4.w + bf_hi(bw.y)) * 0.125f : -INFINITY;
            v[j] = s4;
            mx = fmaxf(mx, fmaxf(fmaxf(s4.x, s4.y), fmaxf(s4.z, s4.w)));
        }
#pragma unroll
        for (int o = 16; o; o >>= 1) mx = fmaxf(mx, __shfl_xor_sync(0xffffffffu, mx, o));
        float sum = 0.0f;
#pragma unroll
        for (int j = 0; j < 8; j++) {
            v[j].x = __expf(v[j].x - mx); v[j].y = __expf(v[j].y - mx);
            v[j].z = __expf(v[j].z - mx); v[j].w = __expf(v[j].w - mx);
            sum += v[j].x + v[j].y + v[j].z + v[j].w;
        }
#pragma unroll
        for (int o = 16; o; o >>= 1) sum += __shfl_xor_sync(0xffffffffu, sum, o);
        float inv = 1.0f / sum;
#pragma unroll
        for (int j = 0; j < 8; j++) {
            v[j].x *= inv; v[j].y *= inv; v[j].z *= inv; v[j].w *= inv;
            int c4 = lane + j * 32;
            __stcs((float4*)(attnb + (size_t)r * 1024 + c4 * 4), v[j]);
            uint32_t h0 = packbf(v[j].x, v[j].y), h1 = packbf(v[j].z, v[j].w);
            PS[r * 1028 + c4 * 2]     = h0;
            PS[r * 1028 + c4 * 2 + 1] = h1;
            PS[r * 1028 + 512 + c4 * 2]     = packbf(v[j].x - bf_lo(h0), v[j].y - bf_hi(h0));
            PS[r * 1028 + 512 + c4 * 2 + 1] = packbf(v[j].z - bf_lo(h1), v[j].w - bf_hi(h1));
        }
    }
    __syncthreads();

    // ---- phase 3: O = P V (full split); P fragments via LDSM x4 ----
    uint32_t* KVh = Kst;             // [64][68]
    uint32_t* KVl = Kst + FW_KST;
    float accO[2][4] = {};
    for (int kt = 0; kt < 8; kt++) {
#pragma unroll
        for (int t = 0; t < 4; t++) {
            int f = tid + t * 256;
            int p = f >> 4, d4 = (f & 15) * 4;
            const float* vp0 = Vb + (kt * 128 + 2 * p) * 64 + d4;
            float4 v0 = *(const float4*)vp0;
            float4 v1 = *(const float4*)(vp0 + 64);
            uint32_t w0 = packbf(v0.x, v1.x), w1 = packbf(v0.y, v1.y);
            uint32_t w2 = packbf(v0.z, v1.z), w3 = packbf(v0.w, v1.w);
            KVh[(d4 + 0) * 68 + p] = w0; KVh[(d4 + 1) * 68 + p] = w1;
            KVh[(d4 + 2) * 68 + p] = w2; KVh[(d4 + 3) * 68 + p] = w3;
            KVl[(d4 + 0) * 68 + p] = packbf(v0.x - bf_lo(w0), v1.x - bf_hi(w0));
            KVl[(d4 + 1) * 68 + p] = packbf(v0.y - bf_lo(w1), v1.y - bf_hi(w1));
            KVl[(d4 + 2) * 68 + p] = packbf(v0.z - bf_lo(w2), v1.z - bf_hi(w2));
            KVl[(d4 + 3) * 68 + p] = packbf(v0.w - bf_lo(w3), v1.w - bf_hi(w3));
        }
        __syncthreads();
#pragma unroll
        for (int c = 0; c < 8; c++) {
            int kb = c * 8 + (lane & 3);
            uint32_t ah[2][4], al[2][4];
#pragma unroll
            for (int mi = 0; mi < 2; mi++) {
                // tiles: [(m,ch0),(m+8,ch0),(m,ch1),(m+8,ch1)]
                uint32_t aaddr = psb +
                    ((mi * 16 + (lt & 1) * 8 + lr) * 1028 + kt * 64 + c * 8 + (lt >> 1) * 4) * 4;
                ldsm4(ah[mi], aaddr);
                ldsm4(al[mi], aaddr + 512 * 4);
            }
            int n = warp * 8 + (lane >> 2);
            uint32_t bvh[2] = { KVh[n * 68 + kb], KVh[n * 68 + kb + 4] };
            uint32_t bvl[2] = { KVl[n * 68 + kb], KVl[n * 68 + kb + 4] };
#pragma unroll
            for (int mi = 0; mi < 2; mi++) {
                mma16(accO[mi], ah[mi], bvh);
                mma16(accO[mi], ah[mi], bvl);
                mma16(accO[mi], al[mi], bvh);
            }
        }
        __syncthreads();
    }
#pragma unroll
    for (int mi = 0; mi < 2; mi++) {
        int r0 = q0 + mi * 16 + (lane >> 2);
        int col = h * 64 + warp * 8 + (lane & 3) * 2;
        *(float2*)&Obuf[(size_t)(b * 1024 + r0) * 512 + col]     = make_float2(accO[mi][0], accO[mi][1]);
        *(float2*)&Obuf[(size_t)(b * 1024 + r0 + 8) * 512 + col] = make_float2(accO[mi][2], accO[mi][3]);
    }
}

// ---------------------------------------------------------------------------
extern "C" void kernel_launch(void* const* d_in, const int* in_sizes, int n_in,
                              void* d_out, int out_size)
{
    const float* q    = (const float*)d_in[0];
    const float* kv   = (const float*)d_in[1];
    const int*   mask = (const int*)d_in[2];
    const float* Wq   = (const float*)d_in[3];
    const float* bq   = (const float*)d_in[4];
    const float* Wk   = (const float*)d_in[5];
    const float* bk   = (const float*)d_in[6];
    const float* Wv   = (const float*)d_in[7];
    const float* bv   = (const float*)d_in[8];
    const float* Wo   = (const float*)d_in[9];
    const float* bo   = (const float*)d_in[10];
    const float* R    = (const float*)d_in[11];

    float* out = (float*)d_out;
    const size_t OUT0_ELEMS = (size_t)B_ * NQ_ * DQ_;
    const size_t ATTN_ELEMS = (size_t)BH_ * NQ_ * NKV_;

    uint32_t *Qh, *Ql, *Kh, *Kl;
    float *Vp, *Ob, *scr;
    cudaGetSymbolAddress((void**)&Qh, g_Qh);
    cudaGetSymbolAddress((void**)&Ql, g_Ql);
    cudaGetSymbolAddress((void**)&Kh, g_Kh);
    cudaGetSymbolAddress((void**)&Kl, g_Kl);
    cudaGetSymbolAddress((void**)&Vp, g_Vp);
    cudaGetSymbolAddress((void**)&Ob, g_Obuf);
    cudaGetSymbolAddress((void**)&scr, g_attn_scratch);

    float* attn = ((size_t)out_size >= OUT0_ELEMS + ATTN_ELEMS) ? (out + OUT0_ELEMS)
                                                                : scr + ATTN_ELEMS / 2;
    uint32_t* biasw = (uint32_t*)scr;

    static cudaStream_t s1 = nullptr, s2 = nullptr;
    static cudaEvent_t eRoot, e1, e2;
    static int init_done = 0;
    if (!init_done) {
        cudaFuncSetAttribute(fused_attn, cudaFuncAttributeMaxDynamicSharedMemorySize,
                             FUSED_WORDS * 4);
        cudaStreamCreateWithFlags(&s1, cudaStreamNonBlocking);
        cudaStreamCreateWithFlags(&s2, cudaStreamNonBlocking);
        cudaEventCreateWithFlags(&eRoot, cudaEventDisableTiming);
        cudaEventCreateWithFlags(&e1, cudaEventDisableTiming);
        cudaEventCreateWithFlags(&e2, cudaEventDisableTiming);
        init_done = 1;
    }

    cudaEventRecord(eRoot, 0);
    cudaStreamWaitEvent(s1, eRoot, 0);
    cudaStreamWaitEvent(s2, eRoot, 0);

    // K projection -> packed hi/lo  (side stream)
    mma_gemm<128,128,32,64,32,false,5,3><<<dim3(4,64,1),256,0,s1>>>(
        kv, Wk, bk, (float*)Kh, (float*)Kl, 512, 512, 512, 0, 0, 0, 0);
    // V projection -> fp32 scatter  (side stream)
    mma_gemm<128,128,32,64,32,false,1,3><<<dim3(4,64,1),256,0,s2>>>(
        kv, Wv, bv, Vp, nullptr, 512, 512, 512, 0, 0, 0, 0);

    // Q projection -> packed hi/lo  (main stream)
    mma_gemm<128,128,32,64,32,false,5,3><<<dim3(4,64,1),256>>>(
        q, Wq, bq, (float*)Qh, (float*)Ql, 512, 512, 512, 0, 0, 0, 0);

    // RPE bias from prepacked Q hi (APACK, NSPLIT=1, MINBLK=4)
    mma_gemm<64,128,32,32,32,true,4,1,4,true><<<dim3(8,1,1024),256>>>(
        (const float*)Qh, R, nullptr, (float*)biasw, nullptr, 64,
        /*lda(words)=*/32768, /*ldb=*/64, /*ldc=*/524288,
        /*sA(words)=*/32, /*sB=*/65536, /*sC=*/512);

    cudaEventRecord(e1, s1);
    cudaEventRecord(e2, s2);
    cudaStreamWaitEvent(0, e1, 0);
    cudaStreamWaitEvent(0, e2, 0);

    // Marker so ncu -s 5 profiles fused_attn next round.
    marker_kernel<<<1, 32>>>();

    // Fused QK^T + bias + mask/scale + softmax + AV
    fused_attn<<<dim3(NQ_/32, BH_), 256, FUSED_WORDS * 4>>>(
        Qh, Ql, Kh, Kl, Vp, mask, biasw, attn, Ob);

    // Out projection
    mma_gemm<128,128,32,64,32,false,0,3><<<dim3(4,64,1),256>>>(
        Ob, Wo, bo, out, nullptr, 512, 512, 512, 512, 0, 0, 0);
}

// round 16
// speedup vs baseline: 1.0666x; 1.0131x over previous
#include <cuda_runtime.h>
#include <cstdint>
#include <cstddef>
#include <math.h>

#define B_   8
#define NQ_  1024
#define NKV_ 1024
#define DQ_  512
#define H_   8
#define DH_  64
#define BH_  64

// Prepacked bf16 hi/lo operand arrays: [bh][n][32] u32 words
__device__ uint32_t g_Qh[BH_ * NQ_ * 32];
__device__ uint32_t g_Ql[BH_ * NQ_ * 32];
__device__ uint32_t g_Kh[BH_ * NKV_ * 32];
__device__ uint32_t g_Kl[BH_ * NKV_ * 32];
__device__ float    g_Vp[BH_ * NKV_ * DH_];   // fp32 [bh,k,d]
__device__ float    g_Obuf[B_ * NQ_ * H_ * DH_];
__device__ float    g_attn_scratch[(size_t)BH_ * NQ_ * NKV_];

__device__ __forceinline__ uint32_t packbf(float x0, float x1) {
    uint32_t r;
    asm("cvt.rn.bf16x2.f32 %0, %1, %2;" : "=r"(r) : "f"(x1), "f"(x0));
    return r;
}
__device__ __forceinline__ float bf_lo(uint32_t r) { return __uint_as_float(r << 16); }
__device__ __forceinline__ float bf_hi(uint32_t r) { return __uint_as_float(r & 0xffff0000u); }

__device__ __forceinline__ void mma16(float* c, const uint32_t* a, const uint32_t* b) {
    asm volatile(
        "mma.sync.aligned.m16n8k16.row.col.f32.bf16.bf16.f32 "
        "{%0,%1,%2,%3},{%4,%5,%6,%7},{%8,%9},{%0,%1,%2,%3};"
        : "+f"(c[0]), "+f"(c[1]), "+f"(c[2]), "+f"(c[3])
        : "r"(a[0]), "r"(a[1]), "r"(a[2]), "r"(a[3]), "r"(b[0]), "r"(b[1]));
}

__device__ __forceinline__ void ldsm4(uint32_t* r, uint32_t addr) {
    asm volatile("ldmatrix.sync.aligned.m8n8.x4.shared.b16 {%0,%1,%2,%3}, [%4];"
        : "=r"(r[0]), "=r"(r[1]), "=r"(r[2]), "=r"(r[3]) : "r"(addr));
}

__device__ __forceinline__ void cp16(uint32_t dst, const void* src) {
    asm volatile("cp.async.ca.shared.global [%0], [%1], 16;" :: "r"(dst), "l"(src));
}
#define CP_COMMIT() asm volatile("cp.async.commit_group;")
#define CP_WAIT0()  asm volatile("cp.async.wait_group 0;")
#define CP_WAIT1()  asm volatile("cp.async.wait_group 1;")

// ---------------------------------------------------------------------------
// Generic GEMM on bf16 tensor cores with split-bf16 accuracy.  (R8 verbatim)
// ---------------------------------------------------------------------------
template <int BM, int BN, int BK, int WM, int WN, bool BCOL, int EPI, int NSPLIT,
          int MINBLK = 1, bool APACK = false>
__global__ __launch_bounds__(256, MINBLK) void mma_gemm(
    const float* __restrict__ A, const float* __restrict__ Bg,
    const float* __restrict__ bias, float* __restrict__ C,
    float* __restrict__ C2,
    int K, long lda, long ldb, long ldc, long sA, long sB, long sC)
{
    constexpr int MT = WM / 16, NT = WN / 8;
    constexpr int WX = BN / WN;
    constexpr int KW = BK / 2;
    constexpr bool SPL = (NSPLIT == 3);
    constexpr int BR  = BCOL ? BN : KW;
    constexpr int BCW = BCOL ? (KW + 4) : (BN + 8);

    __shared__ uint32_t sAh[BM][KW + 4];
    __shared__ uint32_t sAl[SPL ? BM : 1][SPL ? KW + 4 : 1];
    __shared__ uint32_t sBh[BR][BCW];
    __shared__ uint32_t sBl[SPL ? BR : 1][SPL ? BCW : 1];

    const int tid = threadIdx.x;
    const int warp = tid >> 5, lane = tid & 31;
    const int wx = warp % WX, wy = warp / WX;
    const long z = blockIdx.z;

    const float* Ab = APACK ? nullptr : (A + z * sA + (long)blockIdx.y * BM * lda);
    const uint32_t* Abw = APACK ? ((const uint32_t*)A + z * sA + (long)blockIdx.y * BM * lda)
                                : nullptr;
    const float* Bb = BCOL ? (Bg + z * sB + (long)blockIdx.x * BN * ldb)
                           : (Bg + z * sB + (long)blockIdx.x * BN);

    float acc[MT * NT][4];
#pragma unroll
    for (int i = 0; i < MT * NT; i++)
#pragma unroll
        for (int r = 0; r < 4; r++) acc[i][r] = 0.0f;

    for (int k0 = 0; k0 < K; k0 += BK) {
        if (APACK) {
            constexpr int TOT = BM * (KW / 4);
#pragma unroll
            for (int it = 0; it < (TOT + 255) / 256; it++) {
                int idx = tid + it * 256;
                if (TOT % 256 != 0 && idx >= TOT) break;
                int m = idx / (KW / 4), w4 = (idx % (KW / 4)) * 4;
                uint4 v = *(const uint4*)(Abw + (long)m * lda + (k0 >> 1) + w4);
                *(uint4*)&sAh[m][w4] = v;
            }
        } else {
            constexpr int AIT = (BM * BK / 4) / 256;
#pragma unroll
            for (int it = 0; it < AIT; it++) {
                int idx = tid + it * 256;
                int m = idx / (BK / 4), kq = idx % (BK / 4);
                float4 v = *(const float4*)(Ab + (long)m * lda + k0 + kq * 4);
                uint32_t h0 = packbf(v.x, v.y), h1 = packbf(v.z, v.w);
                sAh[m][kq * 2] = h0; sAh[m][kq * 2 + 1] = h1;
                if (SPL) {
                    sAl[m][kq * 2]     = packbf(v.x - bf_lo(h0), v.y - bf_hi(h0));
                    sAl[m][kq * 2 + 1] = packbf(v.z - bf_lo(h1), v.w - bf_hi(h1));
                }
            }
        }
        if (BCOL) {
            constexpr int BIT = (BN * BK / 4) / 256;
#pragma unroll
            for (int it = 0; it < BIT; it++) {
                int idx = tid + it * 256;
                int n = idx / (BK / 4), kq = idx % (BK / 4);
                float4 v = *(const float4*)(Bb + (long)n * ldb + k0 + kq * 4);
                uint32_t h0 = packbf(v.x, v.y), h1 = packbf(v.z, v.w);
                sBh[n][kq * 2] = h0; sBh[n][kq * 2 + 1] = h1;
                if (SPL) {
                    sBl[n][kq * 2]     = packbf(v.x - bf_lo(h0), v.y - bf_hi(h0));
                    sBl[n][kq * 2 + 1] = packbf(v.z - bf_lo(h1), v.w - bf_hi(h1));
                }
            }
        } else {
            constexpr int BIT = (KW * (BN / 4) + 255) / 256;
#pragma unroll
            for (int it = 0; it < BIT; it++) {
                int idx = tid + it * 256;
                if (KW * (BN / 4) % 256 != 0 && idx >= KW * (BN / 4)) break;
                int kp = idx / (BN / 4), n4 = (idx % (BN / 4)) * 4;
                float4 v0 = *(const float4*)(Bb + (long)(k0 + kp * 2) * ldb + n4);
                float4 v1 = *(const float4*)(Bb + (long)(k0 + kp * 2 + 1) * ldb + n4);
                uint32_t h0 = packbf(v0.x, v1.x), h1 = packbf(v0.y, v1.y);
                uint32_t h2 = packbf(v0.z, v1.z), h3 = packbf(v0.w, v1.w);
                sBh[kp][n4 + 0] = h0; sBh[kp][n4 + 1] = h1;
                sBh[kp][n4 + 2] = h2; sBh[kp][n4 + 3] = h3;
                if (SPL) {
                    sBl[kp][n4 + 0] = packbf(v0.x - bf_lo(h0), v1.x - bf_hi(h0));
                    sBl[kp][n4 + 1] = packbf(v0.y - bf_lo(h1), v1.y - bf_hi(h1));
                    sBl[kp][n4 + 2] = packbf(v0.z - bf_lo(h2), v1.z - bf_hi(h2));
                    sBl[kp][n4 + 3] = packbf(v0.w - bf_lo(h3), v1.w - bf_hi(h3));
                }
            }
        }
        __syncthreads();

#pragma unroll
        for (int kc = 0; kc < KW; kc += 8) {
            const int kb = kc + (lane & 3);
            const int mrow = wy * WM + (lane >> 2);
            uint32_t afh[MT][4], afl[MT][4];
#pragma unroll
            for (int i = 0; i < MT; i++) {
                int m = mrow + i * 16;
                afh[i][0] = sAh[m][kb];     afh[i][1] = sAh[m + 8][kb];
                afh[i][2] = sAh[m][kb + 4]; afh[i][3] = sAh[m + 8][kb + 4];
                if (SPL) {
                    afl[i][0] = sAl[m][kb];     afl[i][1] = sAl[m + 8][kb];
                    afl[i][2] = sAl[m][kb + 4]; afl[i][3] = sAl[m + 8][kb + 4];
                }
            }
#pragma unroll
            for (int j = 0; j < NT; j++) {
                uint32_t bfh[2], bfl[2];
                int n = wx * WN + j * 8 + (lane >> 2);
                if (BCOL) {
                    bfh[0] = sBh[n][kb]; bfh[1] = sBh[n][kb + 4];
                    if (SPL) { bfl[0] = sBl[n][kb]; bfl[1] = sBl[n][kb + 4]; }
                } else {
                    bfh[0] = sBh[kb][n]; bfh[1] = sBh[kb + 4][n];
                    if (SPL) { bfl[0] = sBl[kb][n]; bfl[1] = sBl[kb + 4][n]; }
                }
#pragma unroll
                for (int i = 0; i < MT; i++) {
                    mma16(acc[i * NT + j], afh[i], bfh);
                    if (SPL) {
                        mma16(acc[i * NT + j], afh[i], bfl);
                        mma16(acc[i * NT + j], afl[i], bfh);
                    }
                }
            }
        }
        __syncthreads();
    }

    const long m0 = (long)blockIdx.y * BM + wy * WM;
    const long n0 = (long)blockIdx.x * BN + wx * WN;
    float* Cb = C + z * sC;
    long ldcc = ldc;

#pragma unroll
    for (int i = 0; i < MT; i++) {
#pragma unroll
        for (int j = 0; j < NT; j++) {
#pragma unroll
            for (int r2 = 0; r2 < 2; r2++) {
                long row = m0 + i * 16 + r2 * 8 + (lane >> 2);
                long col = n0 + j * 8 + (lane & 3) * 2;
                float v0 = acc[i * NT + j][r2 * 2 + 0];
                float v1 = acc[i * NT + j][r2 * 2 + 1];
                if ((EPI == 0 || EPI == 1) && bias) { v0 += bias[col]; v1 += bias[col + 1]; }
                if (EPI == 1) {
                    long bb = row >> 10, ns = row & 1023;
                    long h = col >> 6, d = col & 63;
                    float* p = C + (((bb * 8 + h) * 1024 + ns) * 64 + d);
                    *(float2*)p = make_float2(v0, v1);
                } else if (EPI == 4) {
                    uint32_t* P = (uint32_t*)C;
                    __stcs(P + row * ldcc + z * sC + (col >> 1), packbf(v0, v1));
                } else if (EPI == 5) {
                    float w0 = v0 + (bias ? bias[col] : 0.0f);
                    float w1 = v1 + (bias ? bias[col + 1] : 0.0f);
                    uint32_t hw = packbf(w0, w1);
                    uint32_t lw = packbf(w0 - bf_lo(hw), w1 - bf_hi(hw));
                    long bb = row >> 10, ns = row & 1023;
                    long hh = col >> 6, d = col & 63;
                    long widx = ((bb * 8 + hh) * 1024 + ns) * 32 + (d >> 1);
                    ((uint32_t*)C)[widx]  = hw;
                    ((uint32_t*)C2)[widx] = lw;
                } else {
                    *(float2*)(Cb + row * ldcc + col) = make_float2(v0, v1);
                }
            }
        }
    }
}

// ---------------------------------------------------------------------------
// Fused attention: R15 (LDSM + hoisted Q) + phase-3 V double-buffer with
// one barrier per kt and preloaded V registers.
// Grid (NQ/32, BH), 256 threads, 2-stage cp.async K pipeline.
// ---------------------------------------------------------------------------
#define FW_S   (32*1028)
#define FW_Q   (32*36)
#define FW_KST (128*36)
#define FW_VST (64*68)                 // one V plane (hi or lo)
#define FUSED_WORDS (FW_S + 2*FW_Q + 4*FW_KST)

__global__ __launch_bounds__(256, 1) void fused_attn(
    const uint32_t* __restrict__ Qhw, const uint32_t* __restrict__ Qlw,
    const uint32_t* __restrict__ Khw, const uint32_t* __restrict__ Klw,
    const float* __restrict__ Vp, const int* __restrict__ mask,
    const uint32_t* __restrict__ biasw, float* __restrict__ attn,
    float* __restrict__ Obuf)
{
    extern __shared__ uint32_t sm[];
    float*    S    = (float*)sm;               // [32][1028] scores / packed P
    uint32_t* PS   = sm;                       // P hi at row+0, lo at row+512
    uint32_t* sQh  = sm + FW_S;                // [32][36]
    uint32_t* sQl  = sQh + FW_Q;
    uint32_t* Kst  = sQl + FW_Q;               // 2 stages x (hi,lo) [128][36]
    const uint32_t psb  = (uint32_t)__cvta_generic_to_shared(sm);
    const uint32_t stgb = (uint32_t)__cvta_generic_to_shared(Kst);

    const int tid = threadIdx.x, warp = tid >> 5, lane = tid & 31;
    const int q0 = blockIdx.x * 32, bh = blockIdx.y;
    const int b = bh >> 3, h = bh & 7;

    const uint32_t* QhB = Qhw + (size_t)bh * 32768 + q0 * 32;
    const uint32_t* QlB = Qlw + (size_t)bh * 32768 + q0 * 32;
    const uint32_t* KhB = Khw + (size_t)bh * 32768;
    const uint32_t* KlB = Klw + (size_t)bh * 32768;
    const float* Vb = Vp + (size_t)bh * 65536;
    float* attnb = attn + (size_t)bh * 1048576 + (size_t)q0 * 1024;
    const uint32_t* biasb = biasw + (size_t)bh * 524288 + (size_t)q0 * 512;

    // issue K tiles 0,1 into stages 0,1
#pragma unroll
    for (int s = 0; s < 2; s++) {
        uint32_t dH = stgb + (s * 2 * FW_KST) * 4;
        uint32_t dL = dH + FW_KST * 4;
        const uint32_t* sH = KhB + s * 128 * 32;
        const uint32_t* sL = KlB + s * 128 * 32;
#pragma unroll
        for (int c = 0; c < 4; c++) {
            int f = tid + c * 256;
            int r = f >> 3, ch = (f & 7) * 4;
            cp16(dH + (r * 36 + ch) * 4, sH + r * 32 + ch);
            cp16(dL + (r * 36 + ch) * 4, sL + r * 32 + ch);
        }
        CP_COMMIT();
    }

    // stage Q (prepacked)
    {
        int m = tid >> 3, w = (tid & 7) * 4;
        *(uint4*)&sQh[m * 36 + w] = *(const uint4*)(QhB + m * 32 + w);
        *(uint4*)&sQl[m * 36 + w] = *(const uint4*)(QlB + m * 32 + w);
    }
    __syncthreads();

    // Hoist Q fragments into registers ONCE (R13 win).
    uint32_t qfh[2][4][4], qfl[2][4][4];
    {
        const int lc = lane & 3, r4 = lane >> 2;
#pragma unroll
        for (int c = 0; c < 4; c++) {
            int kb = c * 8 + lc;
#pragma unroll
            for (int mi = 0; mi < 2; mi++) {
                int m = mi * 16 + r4;
                qfh[mi][c][0] = sQh[m * 36 + kb];     qfh[mi][c][1] = sQh[(m + 8) * 36 + kb];
                qfh[mi][c][2] = sQh[m * 36 + kb + 4]; qfh[mi][c][3] = sQh[(m + 8) * 36 + kb + 4];
                qfl[mi][c][0] = sQl[m * 36 + kb];     qfl[mi][c][1] = sQl[(m + 8) * 36 + kb];
                qfl[mi][c][2] = sQl[m * 36 + kb + 4]; qfl[mi][c][3] = sQl[(m + 8) * 36 + kb + 4];
            }
        }
    }

    const int lt = lane >> 3, lr = lane & 7;   // ldmatrix lane decomposition

    // ---- phase 1: S = Q K^T (split bf16); K fragments via LDSM x4 ----
    for (int kt = 0; kt < 8; kt++) {
        if (kt < 7) { CP_WAIT1(); } else { CP_WAIT0(); }
        __syncthreads();
        const uint32_t kbase = stgb + ((kt & 1) * 2 * FW_KST) * 4;
        float acc[2][2][4] = {};
#pragma unroll
        for (int c = 0; c < 4; c++) {
            uint32_t bfh[4], bfl[4];
            uint32_t kaddr = kbase +
                ((warp * 16 + (lt >> 1) * 8 + lr) * 36 + c * 8 + (lt & 1) * 4) * 4;
            ldsm4(bfh, kaddr);
            ldsm4(bfl, kaddr + FW_KST * 4);
#pragma unroll
            for (int mi = 0; mi < 2; mi++) {
                mma16(acc[mi][0], qfh[mi][c], &bfh[0]);
                mma16(acc[mi][0], qfh[mi][c], &bfl[0]);
                mma16(acc[mi][0], qfl[mi][c], &bfh[0]);
                mma16(acc[mi][1], qfh[mi][c], &bfh[2]);
                mma16(acc[mi][1], qfh[mi][c], &bfl[2]);
                mma16(acc[mi][1], qfl[mi][c], &bfh[2]);
            }
        }
#pragma unroll
        for (int mi = 0; mi < 2; mi++)
#pragma unroll
            for (int nj = 0; nj < 2; nj++) {
                int r = mi * 16 + (lane >> 2);
                int cc = kt * 128 + warp * 16 + nj * 8 + (lane & 3) * 2;
                *(float2*)&S[r * 1028 + cc]       = make_float2(acc[mi][nj][0], acc[mi][nj][1]);
                *(float2*)&S[(r + 8) * 1028 + cc] = make_float2(acc[mi][nj][2], acc[mi][nj][3]);
            }
        __syncthreads();
        if (kt + 2 < 8) {
            int s = kt & 1;
            uint32_t dH = stgb + (s * 2 * FW_KST) * 4;
            uint32_t dL = dH + FW_KST * 4;
            const uint32_t* sH = KhB + (kt + 2) * 128 * 32;
            const uint32_t* sL = KlB + (kt + 2) * 128 * 32;
#pragma unroll
            for (int c = 0; c < 4; c++) {
                int f = tid + c * 256;
                int r = f >> 3, ch = (f & 7) * 4;
                cp16(dH + (r * 36 + ch) * 4, sH + r * 32 + ch);
                cp16(dL + (r * 36 + ch) * 4, sL + r * 32 + ch);
            }
            CP_COMMIT();
        }
    }

    // ---- phase 2: softmax -> attn + packed P (hi at +0, lo at +512) ----
    const int4* mrow = (const int4*)(mask + b * 1024);
    for (int rr = 0; rr < 4; rr++) {
        int r = warp * 4 + rr;
        float4 v[8];
        float mx = -INFINITY;
#pragma unroll
        for (int j = 0; j < 8; j++) {
            int c4 = lane + j * 32;
            float4 s4 = *(float4*)&S[r * 1028 + c4 * 4];
            uint2 bw = __ldcs((const uint2*)(biasb + (size_t)r * 512 + c4 * 2));
            int4 mm = mrow[c4];
            s4.x = mm.x ? (s4.x + bf_lo(bw.x)) * 0.125f : -INFINITY;
            s4.y = mm.y ? (s4.y + bf_hi(bw.x)) * 0.125f : -INFINITY;
            s4.z = mm.z ? (s4.z + bf_lo(bw.y)) * 0.125f : -INFINITY;
            s4.w = mm.w ? (s4.w + bf_hi(bw.y)) * 0.125f : -INFINITY;
            v[j] = s4;
            mx = fmaxf(mx, fmaxf(fmaxf(s4.x, s4.y), fmaxf(s4.z, s4.w)));
        }
#pragma unroll
        for (int o = 16; o; o >>= 1) mx = fmaxf(mx, __shfl_xor_sync(0xffffffffu, mx, o));
        float sum = 0.0f;
#pragma unroll
        for (int j = 0; j < 8; j++) {
            v[j].x = __expf(v[j].x - mx); v[j].y = __expf(v[j].y - mx);
            v[j].z = __expf(v[j].z - mx); v[j].w = __expf(v[j].w - mx);
            sum += v[j].x + v[j].y + v[j].z + v[j].w;
        }
#pragma unroll
        for (int o = 16; o; o >>= 1) sum += __shfl_xor_sync(0xffffffffu, sum, o);
        float inv = 1.0f / sum;
#pragma unroll
        for (int j = 0; j < 8; j++) {
            v[j].x *= inv; v[j].y *= inv; v[j].z *= inv; v[j].w *= inv;
            int c4 = lane + j * 32;
            __stcs((float4*)(attnb + (size_t)r * 1024 + c4 * 4), v[j]);
            uint32_t h0 = packbf(v[j].x, v[j].y), h1 = packbf(v[j].z, v[j].w);
            PS[r * 1028 + c4 * 2]     = h0;
            PS[r * 1028 + c4 * 2 + 1] = h1;
            PS[r * 1028 + 512 + c4 * 2]     = packbf(v[j].x - bf_lo(h0), v[j].y - bf_hi(h0));
            PS[r * 1028 + 512 + c4 * 2 + 1] = packbf(v[j].z - bf_lo(h1), v[j].w - bf_hi(h1));
        }
    }

    // ---- phase 3: O = P V; V double-buffered, ONE barrier per kt ----
    const int vp = tid >> 4, vd4 = (tid & 15) * 4;   // conversion indices
    // preconvert V tile 0 into buffer 0 (done before the barrier that also
    // publishes P, merging the phase-2/3 boundary sync)
    {
        uint32_t* Vh = Kst;
        uint32_t* Vl = Kst + FW_VST;
#pragma unroll
        for (int t = 0; t < 4; t++) {
            int p = vp + t * 16;
            const float* vsrc = Vb + (2 * p) * 64 + vd4;
            float4 v0 = *(const float4*)vsrc;
            float4 v1 = *(const float4*)(vsrc + 64);
            Vh[(vd4 + 0) * 68 + p] = packbf(v0.x, v1.x);
            Vh[(vd4 + 1) * 68 + p] = packbf(v0.y, v1.y);
            Vh[(vd4 + 2) * 68 + p] = packbf(v0.z, v1.z);
            Vh[(vd4 + 3) * 68 + p] = packbf(v0.w, v1.w);
            Vl[(vd4 + 0) * 68 + p] = packbf(v0.x - bf_lo(Vh[(vd4 + 0) * 68 + p]), v1.x - bf_hi(Vh[(vd4 + 0) * 68 + p]));
            Vl[(vd4 + 1) * 68 + p] = packbf(v0.y - bf_lo(Vh[(vd4 + 1) * 68 + p]), v1.y - bf_hi(Vh[(vd4 + 1) * 68 + p]));
            Vl[(vd4 + 2) * 68 + p] = packbf(v0.z - bf_lo(Vh[(vd4 + 2) * 68 + p]), v1.z - bf_hi(Vh[(vd4 + 2) * 68 + p]));
            Vl[(vd4 + 3) * 68 + p] = packbf(v0.w - bf_lo(Vh[(vd4 + 3) * 68 + p]), v1.w - bf_hi(Vh[(vd4 + 3) * 68 + p]));
        }
    }
    __syncthreads();

    float accO[2][4] = {};
    for (int kt = 0; kt < 8; kt++) {
        uint32_t* cVh = Kst + (kt & 1) * (2 * FW_VST);
        uint32_t* cVl = cVh + FW_VST;
        // preload next V tile into registers (LDG latency hidden by MMAs)
        float4 nv0[4], nv1[4];
        if (kt < 7) {
#pragma unroll
            for (int t = 0; t < 4; t++) {
                int p = vp + t * 16;
                const float* vsrc = Vb + ((kt + 1) * 128 + 2 * p) * 64 + vd4;
                nv0[t] = *(const float4*)vsrc;
                nv1[t] = *(const float4*)(vsrc + 64);
            }
        }
        // MMAs on current buffer
#pragma unroll
        for (int c = 0; c < 8; c++) {
            int kb = c * 8 + (lane & 3);
            uint32_t ah[2][4], al[2][4];
#pragma unroll
            for (int mi = 0; mi < 2; mi++) {
                uint32_t aaddr = psb +
                    ((mi * 16 + (lt & 1) * 8 + lr) * 1028 + kt * 64 + c * 8 + (lt >> 1) * 4) * 4;
                ldsm4(ah[mi], aaddr);
                ldsm4(al[mi], aaddr + 512 * 4);
            }
            int n = warp * 8 + (lane >> 2);
            uint32_t bvh[2] = { cVh[n * 68 + kb], cVh[n * 68 + kb + 4] };
            uint32_t bvl[2] = { cVl[n * 68 + kb], cVl[n * 68 + kb + 4] };
#pragma unroll
            for (int mi = 0; mi < 2; mi++) {
                mma16(accO[mi], ah[mi], bvh);
                mma16(accO[mi], ah[mi], bvl);
                mma16(accO[mi], al[mi], bvh);
            }
        }
        // convert preloaded registers into the other buffer
        if (kt < 7) {
            uint32_t* nVh = Kst + ((kt + 1) & 1) * (2 * FW_VST);
            uint32_t* nVl = nVh + FW_VST;
#pragma unroll
            for (int t = 0; t < 4; t++) {
                int p = vp + t * 16;
                uint32_t w0 = packbf(nv0[t].x, nv1[t].x), w1 = packbf(nv0[t].y, nv1[t].y);
                uint32_t w2 = packbf(nv0[t].z, nv1[t].z), w3 = packbf(nv0[t].w, nv1[t].w);
                nVh[(vd4 + 0) * 68 + p] = w0; nVh[(vd4 + 1) * 68 + p] = w1;
                nVh[(vd4 + 2) * 68 + p] = w2; nVh[(vd4 + 3) * 68 + p] = w3;
                nVl[(vd4 + 0) * 68 + p] = packbf(nv0[t].x - bf_lo(w0), nv1[t].x - bf_hi(w0));
                nVl[(vd4 + 1) * 68 + p] = packbf(nv0[t].y - bf_lo(w1), nv1[t].y - bf_hi(w1));
                nVl[(vd4 + 2) * 68 + p] = packbf(nv0[t].z - bf_lo(w2), nv1[t].z - bf_hi(w2));
                nVl[(vd4 + 3) * 68 + p] = packbf(nv0[t].w - bf_lo(w3), nv1[t].w - bf_hi(w3));
            }
        }
        __syncthreads();
    }
#pragma unroll
    for (int mi = 0; mi < 2; mi++) {
        int r0 = q0 + mi * 16 + (lane >> 2);
        int col = h * 64 + warp * 8 + (lane & 3) * 2;
        *(float2*)&Obuf[(size_t)(b * 1024 + r0) * 512 + col]     = make_float2(accO[mi][0], accO[mi][1]);
        *(float2*)&Obuf[(size_t)(b * 1024 + r0 + 8) * 512 + col] = make_float2(accO[mi][2], accO[mi][3]);
    }
}

// ---------------------------------------------------------------------------
extern "C" void kernel_launch(void* const* d_in, const int* in_sizes, int n_in,
                              void* d_out, int out_size)
{
    const float* q    = (const float*)d_in[0];
    const float* kv   = (const float*)d_in[1];
    const int*   mask = (const int*)d_in[2];
    const float* Wq   = (const float*)d_in[3];
    const float* bq   = (const float*)d_in[4];
    const float* Wk   = (const float*)d_in[5];
    const float* bk   = (const float*)d_in[6];
    const float* Wv   = (const float*)d_in[7];
    const float* bv   = (const float*)d_in[8];
    const float* Wo   = (const float*)d_in[9];
    const float* bo   = (const float*)d_in[10];
    const float* R    = (const float*)d_in[11];

    float* out = (float*)d_out;
    const size_t OUT0_ELEMS = (size_t)B_ * NQ_ * DQ_;
    const size_t ATTN_ELEMS = (size_t)BH_ * NQ_ * NKV_;

    uint32_t *Qh, *Ql, *Kh, *Kl;
    float *Vp, *Ob, *scr;
    cudaGetSymbolAddress((void**)&Qh, g_Qh);
    cudaGetSymbolAddress((void**)&Ql, g_Ql);
    cudaGetSymbolAddress((void**)&Kh, g_Kh);
    cudaGetSymbolAddress((void**)&Kl, g_Kl);
    cudaGetSymbolAddress((void**)&Vp, g_Vp);
    cudaGetSymbolAddress((void**)&Ob, g_Obuf);
    cudaGetSymbolAddress((void**)&scr, g_attn_scratch);

    float* attn = ((size_t)out_size >= OUT0_ELEMS + ATTN_ELEMS) ? (out + OUT0_ELEMS)
                                                                : scr + ATTN_ELEMS / 2;
    uint32_t* biasw = (uint32_t*)scr;

    static cudaStream_t s1 = nullptr, s2 = nullptr;
    static cudaEvent_t eRoot, e1, e2;
    static int init_done = 0;
    if (!init_done) {
        cudaFuncSetAttribute(fused_attn, cudaFuncAttributeMaxDynamicSharedMemorySize,
                             FUSED_WORDS * 4);
        cudaStreamCreateWithFlags(&s1, cudaStreamNonBlocking);
        cudaStreamCreateWithFlags(&s2, cudaStreamNonBlocking);
        cudaEventCreateWithFlags(&eRoot, cudaEventDisableTiming);
        cudaEventCreateWithFlags(&e1, cudaEventDisableTiming);
        cudaEventCreateWithFlags(&e2, cudaEventDisableTiming);
        init_done = 1;
    }

    cudaEventRecord(eRoot, 0);
    cudaStreamWaitEvent(s1, eRoot, 0);
    cudaStreamWaitEvent(s2, eRoot, 0);

    // K projection -> packed hi/lo  (side stream)
    mma_gemm<128,128,32,64,32,false,5,3><<<dim3(4,64,1),256,0,s1>>>(
        kv, Wk, bk, (float*)Kh, (float*)Kl, 512, 512, 512, 0, 0, 0, 0);
    // V projection -> fp32 scatter  (side stream)
    mma_gemm<128,128,32,64,32,false,1,3><<<dim3(4,64,1),256,0,s2>>>(
        kv, Wv, bv, Vp, nullptr, 512, 512, 512, 0, 0, 0, 0);

    // Q projection -> packed hi/lo  (main stream)
    mma_gemm<128,128,32,64,32,false,5,3><<<dim3(4,64,1),256>>>(
        q, Wq, bq, (float*)Qh, (float*)Ql, 512, 512, 512, 0, 0, 0, 0);

    // RPE bias from prepacked Q hi (APACK, NSPLIT=1, MINBLK=4)
    mma_gemm<64,128,32,32,32,true,4,1,4,true><<<dim3(8,1,1024),256>>>(
        (const float*)Qh, R, nullptr, (float*)biasw, nullptr, 64,
        /*lda(words)=*/32768, /*ldb=*/64, /*ldc=*/524288,
        /*sA(words)=*/32, /*sB=*/65536, /*sC=*/512);

    cudaEventRecord(e1, s1);
    cudaEventRecord(e2, s2);
    cudaStreamWaitEvent(0, e1, 0);
    cudaStreamWaitEvent(0, e2, 0);

    // Fused QK^T + bias + mask/scale + softmax + AV
    fused_attn<<<dim3(NQ_/32, BH_), 256, FUSED_WORDS * 4>>>(
        Qh, Ql, Kh, Kl, Vp, mask, biasw, attn, Ob);

    // Out projection
    mma_gemm<128,128,32,64,32,false,0,3><<<dim3(4,64,1),256>>>(
        Ob, Wo, bo, out, nullptr, 512, 512, 512, 512, 0, 0, 0);
}